// round 13
// baseline (speedup 1.0000x reference)
#include <cuda_runtime.h>
#include <cuda_bf16.h>
#include <cstdint>
#include <cstddef>

#define NDIM 4096
#define DDIM 256
#define NMTOT ((size_t)NDIM * (size_t)NDIM)
#define EPS_R 0.05f
#define N_SINK 30
#define N_FGW 5

// ---------------- device scratch ----------------
__device__ float g_Dgen [NDIM * NDIM];
__device__ float g_Dreal[NDIM * NDIM];
__device__ float g_CW   [NDIM * NDIM];
__device__ float g_CGW  [NDIM * NDIM];
__device__ float g_Kmat [NDIM * NDIM];
__device__ __nv_bfloat16 g_Dg_h[NDIM * NDIM], g_Dg_l[NDIM * NDIM];
__device__ __nv_bfloat16 g_Dr_h[NDIM * NDIM], g_Dr_l[NDIM * NDIM];
__device__ __nv_bfloat16 g_Pt_h[NDIM * NDIM], g_Pt_l[NDIM * NDIM];
__device__ __nv_bfloat16 g_T_h [NDIM * NDIM], g_T_l [NDIM * NDIM];
__device__ __nv_bfloat16 g_Fg_h[NDIM * DDIM], g_Fg_l[NDIM * DDIM];
__device__ __nv_bfloat16 g_Fr_h[NDIM * DDIM], g_Fr_l[NDIM * DDIM];
__device__ float g_x2g[NDIM], g_x2r[NDIM];
__device__ float g_sg2[NDIM], g_sr2[NDIM];
__device__ float g_rg [NDIM], g_rr [NDIM];
__device__ float g_mu [NDIM], g_nu [NDIM];
__device__ float g_u  [NDIM], g_v  [NDIM];
__device__ float g_colpart[16 * NDIM];
__device__ float g_part[8192];
__device__ float g_scal[8];             // 0:cwmax 1:gmax 2:cmax 3:S
__device__ unsigned int g_bar;          // global barrier counter

// ---------------- helpers ----------------
__device__ __forceinline__ uint32_t pack2(float f0, float f1) {
    __nv_bfloat162 p; p.x = __float2bfloat16(f0); p.y = __float2bfloat16(f1);
    return *reinterpret_cast<uint32_t*>(&p);
}
__device__ __forceinline__ void ldm_x4(uint32_t* r, uint32_t a) {
    asm volatile("ldmatrix.sync.aligned.m8n8.x4.shared.b16 {%0,%1,%2,%3}, [%4];"
        : "=r"(r[0]), "=r"(r[1]), "=r"(r[2]), "=r"(r[3]) : "r"(a));
}
__device__ __forceinline__ void mma16816(float* c, const uint32_t* a, const uint32_t* b) {
    asm volatile("mma.sync.aligned.m16n8k16.row.col.f32.bf16.bf16.f32 "
        "{%0,%1,%2,%3}, {%4,%5,%6,%7}, {%8,%9}, {%0,%1,%2,%3};"
        : "+f"(c[0]), "+f"(c[1]), "+f"(c[2]), "+f"(c[3])
        : "r"(a[0]), "r"(a[1]), "r"(a[2]), "r"(a[3]), "r"(b[0]), "r"(b[1]));
}
__device__ __forceinline__ uint32_t smem_u32(const void* p) {
    uint32_t a;
    asm("{ .reg .u64 t; cvta.to.shared.u64 t, %1; cvt.u32.u64 %0, t; }" : "=r"(a) : "l"(p));
    return a;
}
__device__ __forceinline__ void split2(float x, __nv_bfloat16& h, __nv_bfloat16& l) {
    h = __float2bfloat16(x);
    l = __float2bfloat16(x - __bfloat162float(h));
}
#define CP16(dst, src) asm volatile("cp.async.cg.shared.global [%0], [%1], 16;" :: "r"(dst), "l"(src) : "memory")
#define CPC() asm volatile("cp.async.commit_group;" ::: "memory")
#define CPW(n) asm volatile("cp.async.wait_group %0;" :: "n"(n) : "memory")

// ---------------- reductions ----------------
template<int BS>
__device__ __forceinline__ float bsum(float v) {
    static __shared__ float sh[BS];
    int t = threadIdx.x;
    sh[t] = v; __syncthreads();
#pragma unroll
    for (int s = BS / 2; s >= 64; s >>= 1) { if (t < s) sh[t] += sh[t + s]; __syncthreads(); }
    float x = 0.f;
    if (t < 32) {
        x = sh[t] + sh[t + 32];
#pragma unroll
        for (int o = 16; o; o >>= 1) x += __shfl_down_sync(0xffffffffu, x, o);
    }
    __syncthreads();
    return x;
}
template<int BS>
__device__ __forceinline__ float bmax(float v) {
    static __shared__ float sh[BS];
    int t = threadIdx.x;
    sh[t] = v; __syncthreads();
#pragma unroll
    for (int s = BS / 2; s >= 64; s >>= 1) { if (t < s) sh[t] = fmaxf(sh[t], sh[t + s]); __syncthreads(); }
    float x = -3.402823466e38f;
    if (t < 32) {
        x = fmaxf(sh[t], sh[t + 32]);
#pragma unroll
        for (int o = 16; o; o >>= 1) x = fmaxf(x, __shfl_down_sync(0xffffffffu, x, o));
    }
    return x;
}

// ---------------- 3-term split bf16 GEMM, two-level accumulation ----------
// Templated: MODE 0: T out (re-split bf16). 1: CGW epilogue + gmax.
//            2: cdist sqrt epilogue (fp32). 3: CW relu epilogue + max.
// NT = number of K-tiles (K = NT*32). LDK = operand leading dim (elements).
#define STG_T 10240               // one tile: 128 rows * 80B (64B data + 16B pad)
#define STG_S (4 * STG_T)         // Ah,Al,Bh,Bl = 40960
#define SMEM_MM (3 * STG_S)       // 3 stages = 122880
#define BKT 32

template<int MODE, int NT, int LDK>
__global__ void __launch_bounds__(256, 1)
mma_gemm_kernel(const __nv_bfloat16* __restrict__ Ah_, const __nv_bfloat16* __restrict__ Al_,
                const __nv_bfloat16* __restrict__ Bh_, const __nv_bfloat16* __restrict__ Bl_,
                __nv_bfloat16* __restrict__ Oh, __nv_bfloat16* __restrict__ Ol,
                float* __restrict__ Cout, float* __restrict__ partials,
                const float* __restrict__ vx, const float* __restrict__ vy)
{
    extern __shared__ char smem[];
    const uint32_t sb = smem_u32(smem);
    const int tid = threadIdx.x, warp = tid >> 5, lane = tid & 31;
    const int bm = blockIdx.y << 7, bn = blockIdx.x << 7;
    const int wm = (warp >> 2) << 6, wn = (warp & 3) << 5;  // warp tile 64x32

    const char* srcs[4] = {
        (const char*)(Ah_ + (size_t)bm * LDK), (const char*)(Al_ + (size_t)bm * LDK),
        (const char*)(Bh_ + (size_t)bn * LDK), (const char*)(Bl_ + (size_t)bn * LDK) };

    auto load_stage = [&](int slot, int kt) {
        const uint32_t sbase = sb + slot * STG_S;
        const size_t ko = (size_t)kt * (BKT * 2);
#pragma unroll
        for (int i = 0; i < 8; i++) {
            const int tile = i >> 1;
            const int wc = ((i & 1) << 8) + tid;        // 0..511 within tile
            const int row = wc >> 2, cc = wc & 3;
            uint32_t dst = sbase + tile * STG_T + row * 80 + (cc << 4);
            const char* src = srcs[tile] + (size_t)row * (LDK * 2) + ko + (cc << 4);
            CP16(dst, src);
        }
    };

    float acc[4][4][4], accS[4][4][4];
#pragma unroll
    for (int a = 0; a < 4; a++)
#pragma unroll
        for (int b = 0; b < 4; b++)
#pragma unroll
            for (int c = 0; c < 4; c++) { acc[a][b][c] = 0.f; accS[a][b][c] = 0.f; }

    load_stage(0, 0); CPC();
    load_stage(1, 1); CPC();

    const int grp = lane >> 3, l8 = lane & 7;

    for (int kt = 0; kt < NT; kt++) {
        CPW(1);
        __syncthreads();
        if (kt + 2 < NT) load_stage((kt + 2) % 3, kt + 2);
        CPC();
        const uint32_t stb = sb + (kt % 3) * STG_S;
#pragma unroll
        for (int ks = 0; ks < 2; ks++) {
            uint32_t ah[4][4], al[4][4], bh[4][2], bl[4][2], t[4];
            const uint32_t acol = (ks << 5) + ((grp >> 1) << 4);
#pragma unroll
            for (int mi = 0; mi < 4; mi++) {
                uint32_t ro = (uint32_t)(wm + (mi << 4) + ((grp & 1) << 3) + l8) * 80 + acol;
                ldm_x4(ah[mi], stb + 0 * STG_T + ro);
                ldm_x4(al[mi], stb + 1 * STG_T + ro);
            }
            const uint32_t bcol = (ks << 5) + ((grp & 1) << 4);
#pragma unroll
            for (int np = 0; np < 2; np++) {
                uint32_t ro = (uint32_t)(wn + (np << 4) + ((grp >> 1) << 3) + l8) * 80 + bcol;
                ldm_x4(t, stb + 2 * STG_T + ro);
                bh[2 * np][0] = t[0]; bh[2 * np][1] = t[1];
                bh[2 * np + 1][0] = t[2]; bh[2 * np + 1][1] = t[3];
                ldm_x4(t, stb + 3 * STG_T + ro);
                bl[2 * np][0] = t[0]; bl[2 * np][1] = t[1];
                bl[2 * np + 1][0] = t[2]; bl[2 * np + 1][1] = t[3];
            }
#pragma unroll
            for (int mi = 0; mi < 4; mi++)
#pragma unroll
                for (int ni = 0; ni < 4; ni++) {
                    mma16816(acc[mi][ni], ah[mi], bh[ni]);
                    mma16816(acc[mi][ni], ah[mi], bl[ni]);
                    mma16816(acc[mi][ni], al[mi], bh[ni]);
                }
        }
        if ((kt & 15) == 15 || kt == NT - 1) {   // pairwise flush (noise control)
#pragma unroll
            for (int a = 0; a < 4; a++)
#pragma unroll
                for (int b = 0; b < 4; b++)
#pragma unroll
                    for (int c = 0; c < 4; c++) { accS[a][b][c] += acc[a][b][c]; acc[a][b][c] = 0.f; }
        }
    }

    float lmax = 0.f;
#pragma unroll
    for (int mi = 0; mi < 4; mi++) {
        const int r1 = bm + wm + (mi << 4) + (lane >> 2);
        const int r2 = r1 + 8;
        float pA0 = 0.f, pA1 = 0.f, pB0 = 0.f, pB1 = 0.f;
        if (MODE == 1) { pA0 = g_sg2[r1]; pA1 = g_mu[r1]; pB0 = g_sg2[r2]; pB1 = g_mu[r2]; }
        if (MODE >= 2) { pA0 = vx[r1]; pB0 = vx[r2]; }
#pragma unroll
        for (int ni = 0; ni < 4; ni++) {
            const int n1 = bn + wn + (ni << 3) + ((lane & 3) << 1);
            const float c0 = accS[mi][ni][0], c1 = accS[mi][ni][1];
            const float c2 = accS[mi][ni][2], c3 = accS[mi][ni][3];
            if (MODE == 0) {
                __nv_bfloat16 h0, l0, h1, l1;
                split2(c0, h0, l0); split2(c1, h1, l1);
                __nv_bfloat162 ll01{l0, l1};
                *(uint32_t*)(Oh + (size_t)r1 * NDIM + n1) = pack2(c0, c1);
                *(uint32_t*)(Ol + (size_t)r1 * NDIM + n1) = *(uint32_t*)&ll01;
                __nv_bfloat16 h2, l2, h3, l3;
                split2(c2, h2, l2); split2(c3, h3, l3);
                __nv_bfloat162 ll23{l2, l3};
                *(uint32_t*)(Oh + (size_t)r2 * NDIM + n1) = pack2(c2, c3);
                *(uint32_t*)(Ol + (size_t)r2 * NDIM + n1) = *(uint32_t*)&ll23;
            } else if (MODE == 1) {
                const float nu1 = g_nu[n1], nu2 = g_nu[n1 + 1];
                const float s1 = g_sr2[n1], s2 = g_sr2[n1 + 1];
                float v0 = pA0 * nu1 + pA1 * s1 - 2.f * c0;
                float v1 = pA0 * nu2 + pA1 * s2 - 2.f * c1;
                float v2 = pB0 * nu1 + pB1 * s1 - 2.f * c2;
                float v3 = pB0 * nu2 + pB1 * s2 - 2.f * c3;
                lmax = fmaxf(fmaxf(lmax, fabsf(v0)), fmaxf(fabsf(v1), fmaxf(fabsf(v2), fabsf(v3))));
                *(float2*)(Cout + (size_t)r1 * NDIM + n1) = make_float2(v0, v1);
                *(float2*)(Cout + (size_t)r2 * NDIM + n1) = make_float2(v2, v3);
            } else {
                const float q1 = vy[n1], q2 = vy[n1 + 1];
                float d0 = fmaxf(pA0 + q1 - 2.f * c0, 0.f);
                float d1 = fmaxf(pA0 + q2 - 2.f * c1, 0.f);
                float d2 = fmaxf(pB0 + q1 - 2.f * c2, 0.f);
                float d3 = fmaxf(pB0 + q2 - 2.f * c3, 0.f);
                float v0, v1, v2, v3;
                if (MODE == 2) {
                    v0 = (d0 > 0.f) ? sqrtf(d0) : 0.f; v1 = (d1 > 0.f) ? sqrtf(d1) : 0.f;
                    v2 = (d2 > 0.f) ? sqrtf(d2) : 0.f; v3 = (d3 > 0.f) ? sqrtf(d3) : 0.f;
                } else {
                    v0 = d0; v1 = d1; v2 = d2; v3 = d3;
                    lmax = fmaxf(fmaxf(lmax, d0), fmaxf(d1, fmaxf(d2, d3)));
                }
                *(float2*)(Cout + (size_t)r1 * NDIM + n1) = make_float2(v0, v1);
                *(float2*)(Cout + (size_t)r2 * NDIM + n1) = make_float2(v2, v3);
            }
        }
    }
    if (MODE == 1 || MODE == 3) {
        float mm = bmax<256>(lmax);
        if (tid == 0) partials[blockIdx.y * gridDim.x + blockIdx.x] = mm;
    }
}

// ---------------- persistent Sinkhorn kernel ------------------------------
// grid 256 x 256 threads, 2 CTAs/SM guaranteed -> all blocks co-resident.
// Per iteration: row phase (u), barrier, col partials, barrier, col finalize
// (v), barrier. Cross-block data (u, v, colpart) read via __ldcg (L2).
#define SNB 256

__device__ __forceinline__ void gbar(unsigned int& target) {
    __syncthreads();
    if (threadIdx.x == 0) {
        __threadfence();
        atomicAdd(&g_bar, 1u);
        while (atomicAdd(&g_bar, 0u) < target) __nanosleep(64);
    }
    __syncthreads();
    target += SNB;
}

__global__ void __launch_bounds__(256, 2) sinkhorn_kernel(int niter) {
    const int b = blockIdx.x, t = threadIdx.x;
    __shared__ float sh16[16];
    unsigned int target = SNB;
    const float a_val = 1.0f / NDIM;

    for (int it = 0; it < niter; it++) {
        // ---- row phase: u_i = a / (K v)_i
        for (int i = b; i < NDIM; i += SNB) {
            const float4* kr = (const float4*)(g_Kmat + (size_t)i * NDIM);
            float s = 0.f;
            for (int j = t; j < NDIM / 4; j += 256) {
                float4 k = kr[j];
                float4 w = __ldcg(((const float4*)g_v) + j);
                s += k.x * w.x + k.y * w.y + k.z * w.z + k.w * w.w;
            }
            s = bsum<256>(s);
            if (t == 0) g_u[i] = a_val / s;
        }
        gbar(target);
        // ---- col partials: block b -> colchunk b&15, rowchunk b>>4 (256 rows)
        {
            const int col = ((b & 15) << 8) + t;
            const int r0 = (b >> 4) << 8;
            const float* base = g_Kmat + (size_t)r0 * NDIM + col;
            float s0 = 0.f, s1 = 0.f, s2 = 0.f, s3 = 0.f;
#pragma unroll 8
            for (int i = 0; i < 256; i += 4) {
                s0 += base[(size_t)(i + 0) * NDIM] * __ldcg(g_u + r0 + i + 0);
                s1 += base[(size_t)(i + 1) * NDIM] * __ldcg(g_u + r0 + i + 1);
                s2 += base[(size_t)(i + 2) * NDIM] * __ldcg(g_u + r0 + i + 2);
                s3 += base[(size_t)(i + 3) * NDIM] * __ldcg(g_u + r0 + i + 3);
            }
            g_colpart[((b >> 4) << 12) + col] = (s0 + s1) + (s2 + s3);
        }
        gbar(target);
        // ---- col finalize: block b handles 16 cols; last iter also S partial
        if (t < 16) {
            const int col = (b << 4) + t;
            float s = 0.f;
#pragma unroll
            for (int p = 0; p < 16; p++) s += __ldcg(g_colpart + (p << 12) + col);
            float vv = a_val / s;
            g_v[col] = vv;
            sh16[t] = vv * s;
        }
        if (it == niter - 1) {
            __syncthreads();
            if (t == 0) {
                float ss = 0.f;
#pragma unroll
                for (int q = 0; q < 16; q++) ss += sh16[q];
                g_part[b] = ss;
            }
        }
        gbar(target);
    }
    if (b == 0) {                         // S = sum of 256 block partials
        float s = __ldcg(g_part + t);
        s = bsum<256>(s);
        if (t == 0) g_scal[3] = s;
    }
}

__global__ void sink_reset_kernel() {
    int i = blockIdx.x * 256 + threadIdx.x;
    if (i == 0) g_bar = 0u;
    if (i < NDIM) g_v[i] = 1.0f;
}

// ---------------- small kernels ----------------
__global__ void sqnorm_kernel(const float* __restrict__ X, float* __restrict__ out) {
    int i = blockIdx.x;
    float4 a = ((const float4*)(X + (size_t)i * DDIM))[threadIdx.x];
    float s = a.x * a.x + a.y * a.y + a.z * a.z + a.w * a.w;
    s = bsum<64>(s);
    if (threadIdx.x == 0) out[i] = s;
}

__global__ void row_sum_kernel(const float* __restrict__ M, float* __restrict__ out) {
    int i = blockIdx.x;
    const float4* rp = (const float4*)(M + (size_t)i * NDIM);
    float s = 0.f;
    for (int j = threadIdx.x; j < NDIM / 4; j += 256) { float4 a = rp[j]; s += a.x + a.y + a.z + a.w; }
    s = bsum<256>(s);
    if (threadIdx.x == 0) out[i] = s;
}

__global__ void row_sumsq_kernel(const float* __restrict__ M, float* __restrict__ out) {
    int i = blockIdx.x;
    const float4* rp = (const float4*)(M + (size_t)i * NDIM);
    float s = 0.f;
    for (int j = threadIdx.x; j < NDIM / 4; j += 256) {
        float4 a = rp[j];
        s += a.x * a.x + a.y * a.y + a.z * a.z + a.w * a.w;
    }
    s = bsum<256>(s);
    if (threadIdx.x == 0) out[i] = s;
}

__global__ void split2_kernel(const float* __restrict__ src, __nv_bfloat16* __restrict__ dh,
                              __nv_bfloat16* __restrict__ dl, size_t n2) {
    size_t stride = (size_t)gridDim.x * blockDim.x;
    const float2* sp = (const float2*)src;
    uint32_t* hp = (uint32_t*)dh; uint32_t* lp = (uint32_t*)dl;
    for (size_t i = (size_t)blockIdx.x * blockDim.x + threadIdx.x; i < n2; i += stride) {
        float2 f = sp[i];
        __nv_bfloat16 h0, l0, h1, l1;
        split2(f.x, h0, l0); split2(f.y, h1, l1);
        __nv_bfloat162 hh{h0, h1}, ll{l0, l1};
        hp[i] = *(uint32_t*)&hh; lp[i] = *(uint32_t*)&ll;
    }
}

__global__ void transpose_split2_kernel(const float* __restrict__ src,
                                        __nv_bfloat16* __restrict__ dh,
                                        __nv_bfloat16* __restrict__ dl) {
    __shared__ float tile[32][33];
    const int x0 = blockIdx.x << 5, y0 = blockIdx.y << 5;
    const int tx = threadIdx.x, ty = threadIdx.y;
#pragma unroll
    for (int r = ty; r < 32; r += 8)
        tile[r][tx] = src[(size_t)(y0 + r) * NDIM + x0 + tx];
    __syncthreads();
#pragma unroll
    for (int rn = ty; rn < 32; rn += 8) {
        float f = tile[tx][rn];
        __nv_bfloat16 h, l;
        split2(f, h, l);
        size_t o = (size_t)(x0 + rn) * NDIM + y0 + tx;
        dh[o] = h; dl[o] = l;
    }
}

// P marginals (once per FGW iter): col partials with 16 rowchunks of 256 rows
__global__ void colpart_sum_kernel(const float* __restrict__ M) {
    int col = (blockIdx.x << 8) + threadIdx.x;
    int r0 = blockIdx.y << 8;
    const float* base = M + (size_t)r0 * NDIM + col;
    float s0 = 0.f, s1 = 0.f, s2 = 0.f, s3 = 0.f;
#pragma unroll 8
    for (int i = 0; i < 256; i += 4) {
        s0 += base[(size_t)(i + 0) * NDIM]; s1 += base[(size_t)(i + 1) * NDIM];
        s2 += base[(size_t)(i + 2) * NDIM]; s3 += base[(size_t)(i + 3) * NDIM];
    }
    g_colpart[(blockIdx.y << 12) + col] = (s0 + s1) + (s2 + s3);
}

__global__ void colfin_kernel(float* __restrict__ out) {
    int col = (blockIdx.x << 8) + threadIdx.x;
    float s = 0.f;
#pragma unroll
    for (int p = 0; p < 16; p++) s += g_colpart[(p << 12) + col];
    out[col] = s;
}

__global__ void gmax0_kernel(float* __restrict__ partials) {
    const int i = blockIdx.x;
    const float invn = 1.0f / NDIM;
    const float ai = g_sg2[i] * invn;
    const float gi = 2.0f * g_rg[i] * invn * invn;
    const float4* sp = (const float4*)g_sr2;
    const float4* rp = (const float4*)g_rr;
    float m = 0.f;
    for (int j = threadIdx.x; j < NDIM / 4; j += 256) {
        float4 s = sp[j], rr = rp[j];
        m = fmaxf(m, fabsf(ai + s.x * invn - gi * rr.x));
        m = fmaxf(m, fabsf(ai + s.y * invn - gi * rr.y));
        m = fmaxf(m, fabsf(ai + s.z * invn - gi * rr.z));
        m = fmaxf(m, fabsf(ai + s.w * invn - gi * rr.w));
    }
    m = bmax<256>(m);
    if (threadIdx.x == 0) partials[i] = m;
}

template<int ITER0>
__global__ void fusedmax_kernel(float* __restrict__ partials) {
    const int i = blockIdx.x;
    const float invcw = (g_scal[0] > 0.f) ? 1.f / g_scal[0] : 1.f;
    const float invg  = (g_scal[1] > 0.f) ? 1.f / g_scal[1] : 1.f;
    const float invn = 1.0f / NDIM;
    const float ai = g_sg2[i] * invn;
    const float gi = 2.0f * g_rg[i] * invn * invn;
    const float4* cwp = (const float4*)(g_CW + (size_t)i * NDIM);
    const float4* cgp = (const float4*)(g_CGW + (size_t)i * NDIM);
    const float4* sp = (const float4*)g_sr2;
    const float4* rp = (const float4*)g_rr;
    float m = -3.402823466e38f;
    for (int j = threadIdx.x; j < NDIM / 4; j += 256) {
        float4 cw = cwp[j], cg;
        if (ITER0) {
            float4 s = sp[j], rr = rp[j];
            cg.x = ai + s.x * invn - gi * rr.x; cg.y = ai + s.y * invn - gi * rr.y;
            cg.z = ai + s.z * invn - gi * rr.z; cg.w = ai + s.w * invn - gi * rr.w;
        } else cg = cgp[j];
        m = fmaxf(m, 0.5f * cw.x * invcw + 0.5f * cg.x * invg);
        m = fmaxf(m, 0.5f * cw.y * invcw + 0.5f * cg.y * invg);
        m = fmaxf(m, 0.5f * cw.z * invcw + 0.5f * cg.z * invg);
        m = fmaxf(m, 0.5f * cw.w * invcw + 0.5f * cg.w * invg);
    }
    m = bmax<256>(m);
    if (threadIdx.x == 0) partials[i] = m;
}

template<int ITER0>
__global__ void kexp_kernel() {
    const int i = blockIdx.x;
    const float invcw = (g_scal[0] > 0.f) ? 1.f / g_scal[0] : 1.f;
    const float invg  = (g_scal[1] > 0.f) ? 1.f / g_scal[1] : 1.f;
    const float cm = g_scal[2];
    const float sc = (cm > 0.f) ? (-1.f / ((cm + 1e-8f) * EPS_R)) : (-1.f / EPS_R);
    const float invn = 1.0f / NDIM;
    const float ai = g_sg2[i] * invn;
    const float gi = 2.0f * g_rg[i] * invn * invn;
    const float4* cwp = (const float4*)(g_CW + (size_t)i * NDIM);
    const float4* cgp = (const float4*)(g_CGW + (size_t)i * NDIM);
    const float4* sp = (const float4*)g_sr2;
    const float4* rp = (const float4*)g_rr;
    float4* kp = (float4*)(g_Kmat + (size_t)i * NDIM);
    for (int j = threadIdx.x; j < NDIM / 4; j += 256) {
        float4 cw = cwp[j], cg;
        if (ITER0) {
            float4 s = sp[j], rr = rp[j];
            cg.x = ai + s.x * invn - gi * rr.x; cg.y = ai + s.y * invn - gi * rr.y;
            cg.z = ai + s.z * invn - gi * rr.z; cg.w = ai + s.w * invn - gi * rr.w;
        } else cg = cgp[j];
        float4 o;
        o.x = __expf((0.5f * cw.x * invcw + 0.5f * cg.x * invg) * sc);
        o.y = __expf((0.5f * cw.y * invcw + 0.5f * cg.y * invg) * sc);
        o.z = __expf((0.5f * cw.z * invcw + 0.5f * cg.z * invg) * sc);
        o.w = __expf((0.5f * cw.w * invcw + 0.5f * cg.w * invg) * sc);
        kp[j] = o;
    }
}

// P = u_i K_ij v_j / (S + 1e-10)
__global__ void pwrite_kernel(float* __restrict__ P) {
    int i = blockIdx.x;
    float ui = g_u[i];
    float sc = 1.0f / (g_scal[3] + 1e-10f);
    const float4* kr = (const float4*)(g_Kmat + (size_t)i * NDIM);
    const float4* vv = (const float4*)g_v;
    float4* pr = (float4*)(P + (size_t)i * NDIM);
    for (int j = threadIdx.x; j < NDIM / 4; j += 256) {
        float4 k = kr[j], w = vv[j];
        float4 o;
        o.x = sc * (ui * k.x * w.x); o.y = sc * (ui * k.y * w.y);
        o.z = sc * (ui * k.z * w.z); o.w = sc * (ui * k.w * w.w);
        pr[j] = o;
    }
}

__global__ void cfinal_kernel(float* __restrict__ out) {
    size_t stride = (size_t)gridDim.x * blockDim.x;
    const float4* cwp = (const float4*)g_CW;
    const float4* cgp = (const float4*)g_CGW;
    float4* op = (float4*)out;
    for (size_t i = (size_t)blockIdx.x * blockDim.x + threadIdx.x; i < NMTOT / 4; i += stride) {
        float4 cw = cwp[i], cg = cgp[i];
        op[i] = make_float4(0.5f * cw.x + 0.5f * cg.x, 0.5f * cw.y + 0.5f * cg.y,
                            0.5f * cw.z + 0.5f * cg.z, 0.5f * cw.w + 0.5f * cg.w);
    }
}

__global__ void reduce_max_kernel(const float* __restrict__ part, int n, int slot) {
    float m = -3.402823466e38f;
    for (int i = threadIdx.x; i < n; i += 1024) m = fmaxf(m, part[i]);
    m = bmax<1024>(m);
    if (threadIdx.x == 0) g_scal[slot] = m;
}

// ---------------- launch --------------------------------------------------
extern "C" void kernel_launch(void* const* d_in, const int* in_sizes, int n_in,
                              void* d_out, int out_size) {
    const float* fg = (const float*)d_in[0];
    const float* fr = (const float*)d_in[1];
    float* P  = (float*)d_out;
    float* Cf = (float*)d_out + NMTOT;

    float *Dgen, *Dreal, *CW, *CGW, *x2g, *x2r, *sg2, *sr2, *rg, *rr, *nu, *part;
    __nv_bfloat16 *Dgh, *Dgl, *Drh, *Drl, *Pth, *Ptl, *Th, *Tl, *Fgh, *Fgl, *Frh, *Frl;
    cudaGetSymbolAddress((void**)&Dgen, g_Dgen);   cudaGetSymbolAddress((void**)&Dreal, g_Dreal);
    cudaGetSymbolAddress((void**)&CW, g_CW);       cudaGetSymbolAddress((void**)&CGW, g_CGW);
    cudaGetSymbolAddress((void**)&x2g, g_x2g);     cudaGetSymbolAddress((void**)&x2r, g_x2r);
    cudaGetSymbolAddress((void**)&sg2, g_sg2);     cudaGetSymbolAddress((void**)&sr2, g_sr2);
    cudaGetSymbolAddress((void**)&rg, g_rg);       cudaGetSymbolAddress((void**)&rr, g_rr);
    cudaGetSymbolAddress((void**)&nu, g_nu);       cudaGetSymbolAddress((void**)&part, g_part);
    cudaGetSymbolAddress((void**)&Dgh, g_Dg_h);    cudaGetSymbolAddress((void**)&Dgl, g_Dg_l);
    cudaGetSymbolAddress((void**)&Drh, g_Dr_h);    cudaGetSymbolAddress((void**)&Drl, g_Dr_l);
    cudaGetSymbolAddress((void**)&Pth, g_Pt_h);    cudaGetSymbolAddress((void**)&Ptl, g_Pt_l);
    cudaGetSymbolAddress((void**)&Th, g_T_h);      cudaGetSymbolAddress((void**)&Tl, g_T_l);
    cudaGetSymbolAddress((void**)&Fgh, g_Fg_h);    cudaGetSymbolAddress((void**)&Fgl, g_Fg_l);
    cudaGetSymbolAddress((void**)&Frh, g_Fr_h);    cudaGetSymbolAddress((void**)&Frl, g_Fr_l);
    float* mu; cudaGetSymbolAddress((void**)&mu, g_mu);

    cudaFuncSetAttribute((const void*)mma_gemm_kernel<0, 128, NDIM>, cudaFuncAttributeMaxDynamicSharedMemorySize, SMEM_MM);
    cudaFuncSetAttribute((const void*)mma_gemm_kernel<1, 128, NDIM>, cudaFuncAttributeMaxDynamicSharedMemorySize, SMEM_MM);
    cudaFuncSetAttribute((const void*)mma_gemm_kernel<2, 8, DDIM>,  cudaFuncAttributeMaxDynamicSharedMemorySize, SMEM_MM);
    cudaFuncSetAttribute((const void*)mma_gemm_kernel<3, 8, DDIM>,  cudaFuncAttributeMaxDynamicSharedMemorySize, SMEM_MM);

    const dim3 gg(32, 32);
    const dim3 gcol(16, 16);
    const dim3 gtr(128, 128);
    const dim3 btr(32, 8);

    // feature norms + splits, cdist via tensor cores
    sqnorm_kernel<<<NDIM, 64>>>(fg, x2g);
    sqnorm_kernel<<<NDIM, 64>>>(fr, x2r);
    split2_kernel<<<1024, 256>>>(fg, Fgh, Fgl, (size_t)NDIM * DDIM / 2);
    split2_kernel<<<1024, 256>>>(fr, Frh, Frl, (size_t)NDIM * DDIM / 2);
    mma_gemm_kernel<2, 8, DDIM><<<gg, 256, SMEM_MM>>>(Fgh, Fgl, Fgh, Fgl, nullptr, nullptr, Dgen, nullptr, x2g, x2g);
    mma_gemm_kernel<2, 8, DDIM><<<gg, 256, SMEM_MM>>>(Frh, Frl, Frh, Frl, nullptr, nullptr, Dreal, nullptr, x2r, x2r);
    mma_gemm_kernel<3, 8, DDIM><<<gg, 256, SMEM_MM>>>(Fgh, Fgl, Frh, Frl, nullptr, nullptr, CW, part, x2g, x2r);
    reduce_max_kernel<<<1, 1024>>>(part, 1024, 0);           // cwmax

    row_sumsq_kernel<<<NDIM, 256>>>(Dgen, sg2);
    row_sumsq_kernel<<<NDIM, 256>>>(Dreal, sr2);
    row_sum_kernel<<<NDIM, 256>>>(Dgen, rg);
    row_sum_kernel<<<NDIM, 256>>>(Dreal, rr);                // symmetric -> colsum
    split2_kernel<<<4096, 256>>>(Dgen, Dgh, Dgl, NMTOT / 2);
    split2_kernel<<<4096, 256>>>(Dreal, Drh, Drl, NMTOT / 2);  // symmetric -> B^T == B

    for (int it = 0; it < N_FGW; it++) {
        if (it == 0) {
            // coupling = a b^T is rank-1: closed-form CGW0
            gmax0_kernel<<<NDIM, 256>>>(part);
            reduce_max_kernel<<<1, 1024>>>(part, 4096, 1);   // gmax
            fusedmax_kernel<1><<<NDIM, 256>>>(part);
            reduce_max_kernel<<<1, 1024>>>(part, 4096, 2);   // cmax
            kexp_kernel<1><<<NDIM, 256>>>();
        } else {
            row_sum_kernel<<<NDIM, 256>>>(P, mu);
            colpart_sum_kernel<<<gcol, 256>>>(P);
            colfin_kernel<<<16, 256>>>(nu);
            transpose_split2_kernel<<<gtr, btr>>>(P, Pth, Ptl);
            mma_gemm_kernel<0, 128, NDIM><<<gg, 256, SMEM_MM>>>(Dgh, Dgl, Pth, Ptl, Th, Tl, nullptr, nullptr, nullptr, nullptr);
            mma_gemm_kernel<1, 128, NDIM><<<gg, 256, SMEM_MM>>>(Th, Tl, Drh, Drl, nullptr, nullptr, CGW, part, nullptr, nullptr);
            reduce_max_kernel<<<1, 1024>>>(part, 1024, 1);   // gmax
            fusedmax_kernel<0><<<NDIM, 256>>>(part);
            reduce_max_kernel<<<1, 1024>>>(part, 4096, 2);   // cmax
            kexp_kernel<0><<<NDIM, 256>>>();
        }
        // Sinkhorn: single persistent kernel (30 iters, computes S at the end)
        sink_reset_kernel<<<16, 256>>>();
        sinkhorn_kernel<<<SNB, 256>>>(N_SINK);
        pwrite_kernel<<<NDIM, 256>>>(P);                     // P scaled by 1/S
    }
    cfinal_kernel<<<4096, 256>>>(Cf);
}

// round 14
// speedup vs baseline: 1.2872x; 1.2872x over previous
#include <cuda_runtime.h>
#include <cuda_bf16.h>
#include <cstdint>
#include <cstddef>

#define NDIM 4096
#define DDIM 256
#define NMTOT ((size_t)NDIM * (size_t)NDIM)
#define EPS_R 0.05f
#define N_SINK 30
#define N_FGW 5

// ---------------- device scratch ----------------
__device__ float g_Dgen [NDIM * NDIM];
__device__ float g_Dreal[NDIM * NDIM];
__device__ float g_CW   [NDIM * NDIM];
__device__ float g_CGW  [NDIM * NDIM];
__device__ float g_Kmat [NDIM * NDIM];
__device__ __nv_bfloat16 g_Dg_h[NDIM * NDIM], g_Dg_l[NDIM * NDIM];
__device__ __nv_bfloat16 g_Dr_h[NDIM * NDIM], g_Dr_l[NDIM * NDIM];
__device__ __nv_bfloat16 g_Pt_h[NDIM * NDIM], g_Pt_l[NDIM * NDIM];
__device__ __nv_bfloat16 g_T_h [NDIM * NDIM], g_T_l [NDIM * NDIM];
__device__ __nv_bfloat16 g_Fg_h[NDIM * DDIM], g_Fg_l[NDIM * DDIM];
__device__ __nv_bfloat16 g_Fr_h[NDIM * DDIM], g_Fr_l[NDIM * DDIM];
__device__ float g_x2g[NDIM], g_x2r[NDIM];
__device__ float g_sg2[NDIM], g_sr2[NDIM];
__device__ float g_rg [NDIM], g_rr [NDIM];
__device__ float g_mu [NDIM];
__device__ float g_u  [NDIM], g_v  [NDIM];
__device__ float g_colpart[32 * NDIM];
__device__ float g_part[8192];
__device__ float g_scal[8];   // 0:cwmax 1:gmax 2:cmax

// ---------------- helpers ----------------
__device__ __forceinline__ uint32_t pack2(float f0, float f1) {
    __nv_bfloat162 p; p.x = __float2bfloat16(f0); p.y = __float2bfloat16(f1);
    return *reinterpret_cast<uint32_t*>(&p);
}
__device__ __forceinline__ void ldm_x4(uint32_t* r, uint32_t a) {
    asm volatile("ldmatrix.sync.aligned.m8n8.x4.shared.b16 {%0,%1,%2,%3}, [%4];"
        : "=r"(r[0]), "=r"(r[1]), "=r"(r[2]), "=r"(r[3]) : "r"(a));
}
__device__ __forceinline__ void mma16816(float* c, const uint32_t* a, const uint32_t* b) {
    asm volatile("mma.sync.aligned.m16n8k16.row.col.f32.bf16.bf16.f32 "
        "{%0,%1,%2,%3}, {%4,%5,%6,%7}, {%8,%9}, {%0,%1,%2,%3};"
        : "+f"(c[0]), "+f"(c[1]), "+f"(c[2]), "+f"(c[3])
        : "r"(a[0]), "r"(a[1]), "r"(a[2]), "r"(a[3]), "r"(b[0]), "r"(b[1]));
}
__device__ __forceinline__ uint32_t smem_u32(const void* p) {
    uint32_t a;
    asm("{ .reg .u64 t; cvta.to.shared.u64 t, %1; cvt.u32.u64 %0, t; }" : "=r"(a) : "l"(p));
    return a;
}
__device__ __forceinline__ void split2(float x, __nv_bfloat16& h, __nv_bfloat16& l) {
    h = __float2bfloat16(x);
    l = __float2bfloat16(x - __bfloat162float(h));
}
#define CP16(dst, src) asm volatile("cp.async.cg.shared.global [%0], [%1], 16;" :: "r"(dst), "l"(src) : "memory")
#define CPC() asm volatile("cp.async.commit_group;" ::: "memory")
#define CPW(n) asm volatile("cp.async.wait_group %0;" :: "n"(n) : "memory")

// ---------------- reductions ----------------
template<int BS>
__device__ __forceinline__ float bsum(float v) {
    static __shared__ float sh[BS];
    int t = threadIdx.x;
    sh[t] = v; __syncthreads();
#pragma unroll
    for (int s = BS / 2; s >= 64; s >>= 1) { if (t < s) sh[t] += sh[t + s]; __syncthreads(); }
    float x = 0.f;
    if (t < 32) {
        x = sh[t] + sh[t + 32];
#pragma unroll
        for (int o = 16; o; o >>= 1) x += __shfl_down_sync(0xffffffffu, x, o);
    }
    return x;
}
template<int BS>
__device__ __forceinline__ float bmax(float v) {
    static __shared__ float sh[BS];
    int t = threadIdx.x;
    sh[t] = v; __syncthreads();
#pragma unroll
    for (int s = BS / 2; s >= 64; s >>= 1) { if (t < s) sh[t] = fmaxf(sh[t], sh[t + s]); __syncthreads(); }
    float x = -3.402823466e38f;
    if (t < 32) {
        x = fmaxf(sh[t], sh[t + 32]);
#pragma unroll
        for (int o = 16; o; o >>= 1) x = fmaxf(x, __shfl_down_sync(0xffffffffu, x, o));
    }
    return x;
}

// ---------------- 3-term split bf16 GEMM, two-level accumulation ----------
// MODE 0: T out (re-split bf16). 1: CGW epilogue + gmax (nu == 1/NDIM const).
// MODE 2: cdist sqrt epilogue (fp32). 3: CW relu epilogue + max.
// NT = number of K-tiles (K = NT*32). LDK = operand leading dim (elements).
#define STG_T 10240               // one tile: 128 rows * 80B (64B data + 16B pad)
#define STG_S (4 * STG_T)         // Ah,Al,Bh,Bl = 40960
#define SMEM_MM (3 * STG_S)       // 3 stages = 122880
#define BKT 32

template<int MODE, int NT, int LDK>
__global__ void __launch_bounds__(256, 1)
mma_gemm_kernel(const __nv_bfloat16* __restrict__ Ah_, const __nv_bfloat16* __restrict__ Al_,
                const __nv_bfloat16* __restrict__ Bh_, const __nv_bfloat16* __restrict__ Bl_,
                __nv_bfloat16* __restrict__ Oh, __nv_bfloat16* __restrict__ Ol,
                float* __restrict__ Cout, float* __restrict__ partials,
                const float* __restrict__ vx, const float* __restrict__ vy)
{
    extern __shared__ char smem[];
    const uint32_t sb = smem_u32(smem);
    const int tid = threadIdx.x, warp = tid >> 5, lane = tid & 31;
    const int bm = blockIdx.y << 7, bn = blockIdx.x << 7;
    const int wm = (warp >> 2) << 6, wn = (warp & 3) << 5;  // warp tile 64x32

    const char* srcs[4] = {
        (const char*)(Ah_ + (size_t)bm * LDK), (const char*)(Al_ + (size_t)bm * LDK),
        (const char*)(Bh_ + (size_t)bn * LDK), (const char*)(Bl_ + (size_t)bn * LDK) };

    auto load_stage = [&](int slot, int kt) {
        const uint32_t sbase = sb + slot * STG_S;
        const size_t ko = (size_t)kt * (BKT * 2);
#pragma unroll
        for (int i = 0; i < 8; i++) {
            const int tile = i >> 1;
            const int wc = ((i & 1) << 8) + tid;        // 0..511 within tile
            const int row = wc >> 2, cc = wc & 3;
            uint32_t dst = sbase + tile * STG_T + row * 80 + (cc << 4);
            const char* src = srcs[tile] + (size_t)row * (LDK * 2) + ko + (cc << 4);
            CP16(dst, src);
        }
    };

    float acc[4][4][4], accS[4][4][4];
#pragma unroll
    for (int a = 0; a < 4; a++)
#pragma unroll
        for (int b = 0; b < 4; b++)
#pragma unroll
            for (int c = 0; c < 4; c++) { acc[a][b][c] = 0.f; accS[a][b][c] = 0.f; }

    load_stage(0, 0); CPC();
    load_stage(1, 1); CPC();

    const int grp = lane >> 3, l8 = lane & 7;

    for (int kt = 0; kt < NT; kt++) {
        CPW(1);
        __syncthreads();
        if (kt + 2 < NT) load_stage((kt + 2) % 3, kt + 2);
        CPC();
        const uint32_t stb = sb + (kt % 3) * STG_S;
#pragma unroll
        for (int ks = 0; ks < 2; ks++) {
            uint32_t ah[4][4], al[4][4], bh[4][2], bl[4][2], t[4];
            const uint32_t acol = (ks << 5) + ((grp >> 1) << 4);
#pragma unroll
            for (int mi = 0; mi < 4; mi++) {
                uint32_t ro = (uint32_t)(wm + (mi << 4) + ((grp & 1) << 3) + l8) * 80 + acol;
                ldm_x4(ah[mi], stb + 0 * STG_T + ro);
                ldm_x4(al[mi], stb + 1 * STG_T + ro);
            }
            const uint32_t bcol = (ks << 5) + ((grp & 1) << 4);
#pragma unroll
            for (int np = 0; np < 2; np++) {
                uint32_t ro = (uint32_t)(wn + (np << 4) + ((grp >> 1) << 3) + l8) * 80 + bcol;
                ldm_x4(t, stb + 2 * STG_T + ro);
                bh[2 * np][0] = t[0]; bh[2 * np][1] = t[1];
                bh[2 * np + 1][0] = t[2]; bh[2 * np + 1][1] = t[3];
                ldm_x4(t, stb + 3 * STG_T + ro);
                bl[2 * np][0] = t[0]; bl[2 * np][1] = t[1];
                bl[2 * np + 1][0] = t[2]; bl[2 * np + 1][1] = t[3];
            }
#pragma unroll
            for (int mi = 0; mi < 4; mi++)
#pragma unroll
                for (int ni = 0; ni < 4; ni++) {
                    mma16816(acc[mi][ni], ah[mi], bh[ni]);
                    mma16816(acc[mi][ni], ah[mi], bl[ni]);
                    mma16816(acc[mi][ni], al[mi], bh[ni]);
                }
        }
        if ((kt & 15) == 15 || kt == NT - 1) {   // pairwise flush (noise control)
#pragma unroll
            for (int a = 0; a < 4; a++)
#pragma unroll
                for (int b = 0; b < 4; b++)
#pragma unroll
                    for (int c = 0; c < 4; c++) { accS[a][b][c] += acc[a][b][c]; acc[a][b][c] = 0.f; }
        }
    }

    const float invn = 1.0f / NDIM;
    float lmax = 0.f;
#pragma unroll
    for (int mi = 0; mi < 4; mi++) {
        const int r1 = bm + wm + (mi << 4) + (lane >> 2);
        const int r2 = r1 + 8;
        float pA0 = 0.f, pA1 = 0.f, pB0 = 0.f, pB1 = 0.f;
        if (MODE == 1) { pA0 = g_sg2[r1]; pA1 = g_mu[r1]; pB0 = g_sg2[r2]; pB1 = g_mu[r2]; }
        if (MODE >= 2) { pA0 = vx[r1]; pB0 = vx[r2]; }
#pragma unroll
        for (int ni = 0; ni < 4; ni++) {
            const int n1 = bn + wn + (ni << 3) + ((lane & 3) << 1);
            const float c0 = accS[mi][ni][0], c1 = accS[mi][ni][1];
            const float c2 = accS[mi][ni][2], c3 = accS[mi][ni][3];
            if (MODE == 0) {
                __nv_bfloat16 h0, l0, h1, l1;
                split2(c0, h0, l0); split2(c1, h1, l1);
                __nv_bfloat162 ll01{l0, l1};
                *(uint32_t*)(Oh + (size_t)r1 * NDIM + n1) = pack2(c0, c1);
                *(uint32_t*)(Ol + (size_t)r1 * NDIM + n1) = *(uint32_t*)&ll01;
                __nv_bfloat16 h2, l2, h3, l3;
                split2(c2, h2, l2); split2(c3, h3, l3);
                __nv_bfloat162 ll23{l2, l3};
                *(uint32_t*)(Oh + (size_t)r2 * NDIM + n1) = pack2(c2, c3);
                *(uint32_t*)(Ol + (size_t)r2 * NDIM + n1) = *(uint32_t*)&ll23;
            } else if (MODE == 1) {
                const float s1 = g_sr2[n1], s2 = g_sr2[n1 + 1];
                float v0 = pA0 * invn + pA1 * s1 - 2.f * c0;
                float v1 = pA0 * invn + pA1 * s2 - 2.f * c1;
                float v2 = pB0 * invn + pB1 * s1 - 2.f * c2;
                float v3 = pB0 * invn + pB1 * s2 - 2.f * c3;
                lmax = fmaxf(fmaxf(lmax, fabsf(v0)), fmaxf(fabsf(v1), fmaxf(fabsf(v2), fabsf(v3))));
                *(float2*)(Cout + (size_t)r1 * NDIM + n1) = make_float2(v0, v1);
                *(float2*)(Cout + (size_t)r2 * NDIM + n1) = make_float2(v2, v3);
            } else {
                const float q1 = vy[n1], q2 = vy[n1 + 1];
                float d0 = fmaxf(pA0 + q1 - 2.f * c0, 0.f);
                float d1 = fmaxf(pA0 + q2 - 2.f * c1, 0.f);
                float d2 = fmaxf(pB0 + q1 - 2.f * c2, 0.f);
                float d3 = fmaxf(pB0 + q2 - 2.f * c3, 0.f);
                float v0, v1, v2, v3;
                if (MODE == 2) {
                    v0 = (d0 > 0.f) ? sqrtf(d0) : 0.f; v1 = (d1 > 0.f) ? sqrtf(d1) : 0.f;
                    v2 = (d2 > 0.f) ? sqrtf(d2) : 0.f; v3 = (d3 > 0.f) ? sqrtf(d3) : 0.f;
                } else {
                    v0 = d0; v1 = d1; v2 = d2; v3 = d3;
                    lmax = fmaxf(fmaxf(lmax, d0), fmaxf(d1, fmaxf(d2, d3)));
                }
                *(float2*)(Cout + (size_t)r1 * NDIM + n1) = make_float2(v0, v1);
                *(float2*)(Cout + (size_t)r2 * NDIM + n1) = make_float2(v2, v3);
            }
        }
    }
    if (MODE == 1 || MODE == 3) {
        float mm = bmax<256>(lmax);
        if (tid == 0) partials[blockIdx.y * gridDim.x + blockIdx.x] = mm;
    }
}

// ---------------- small kernels ----------------
__global__ void sqnorm_kernel(const float* __restrict__ X, float* __restrict__ out) {
    int i = blockIdx.x;
    float4 a = ((const float4*)(X + (size_t)i * DDIM))[threadIdx.x];
    float s = a.x * a.x + a.y * a.y + a.z * a.z + a.w * a.w;
    s = bsum<64>(s);
    if (threadIdx.x == 0) out[i] = s;
}

__global__ void fill_kernel(float* __restrict__ p, float val, size_t n) {
    size_t stride = (size_t)gridDim.x * blockDim.x;
    for (size_t i = (size_t)blockIdx.x * blockDim.x + threadIdx.x; i < n; i += stride) p[i] = val;
}

__global__ void row_sum_kernel(const float* __restrict__ M, float* __restrict__ out) {
    int i = blockIdx.x;
    const float4* rp = (const float4*)(M + (size_t)i * NDIM);
    float s = 0.f;
    for (int j = threadIdx.x; j < NDIM / 4; j += 256) { float4 a = rp[j]; s += a.x + a.y + a.z + a.w; }
    s = bsum<256>(s);
    if (threadIdx.x == 0) out[i] = s;
}

__global__ void row_sumsq_kernel(const float* __restrict__ M, float* __restrict__ out) {
    int i = blockIdx.x;
    const float4* rp = (const float4*)(M + (size_t)i * NDIM);
    float s = 0.f;
    for (int j = threadIdx.x; j < NDIM / 4; j += 256) {
        float4 a = rp[j];
        s += a.x * a.x + a.y * a.y + a.z * a.z + a.w * a.w;
    }
    s = bsum<256>(s);
    if (threadIdx.x == 0) out[i] = s;
}

__global__ void split2_kernel(const float* __restrict__ src, __nv_bfloat16* __restrict__ dh,
                              __nv_bfloat16* __restrict__ dl, size_t n2) {
    size_t stride = (size_t)gridDim.x * blockDim.x;
    const float2* sp = (const float2*)src;
    uint32_t* hp = (uint32_t*)dh; uint32_t* lp = (uint32_t*)dl;
    for (size_t i = (size_t)blockIdx.x * blockDim.x + threadIdx.x; i < n2; i += stride) {
        float2 f = sp[i];
        __nv_bfloat16 h0, l0, h1, l1;
        split2(f.x, h0, l0); split2(f.y, h1, l1);
        __nv_bfloat162 hh{h0, h1}, ll{l0, l1};
        hp[i] = *(uint32_t*)&hh; lp[i] = *(uint32_t*)&ll;
    }
}

__global__ void transpose_split2_kernel(const float* __restrict__ src,
                                        __nv_bfloat16* __restrict__ dh,
                                        __nv_bfloat16* __restrict__ dl) {
    __shared__ float tile[32][33];
    const int x0 = blockIdx.x << 5, y0 = blockIdx.y << 5;
    const int tx = threadIdx.x, ty = threadIdx.y;
#pragma unroll
    for (int r = ty; r < 32; r += 8)
        tile[r][tx] = src[(size_t)(y0 + r) * NDIM + x0 + tx];
    __syncthreads();
#pragma unroll
    for (int rn = ty; rn < 32; rn += 8) {
        float f = tile[tx][rn];
        __nv_bfloat16 h, l;
        split2(f, h, l);
        size_t o = (size_t)(x0 + rn) * NDIM + y0 + tx;
        dh[o] = h; dl[o] = l;
    }
}

// Sinkhorn kernels (launch-based, R12-proven)
__global__ void sink_row_kernel() {
    int i = blockIdx.x;
    const float4* kr = (const float4*)(g_Kmat + (size_t)i * NDIM);
    const float4* vv = (const float4*)g_v;
    float s = 0.f;
    for (int j = threadIdx.x; j < NDIM / 4; j += 256) {
        float4 k = kr[j], w = vv[j];
        s += k.x * w.x + k.y * w.y + k.z * w.z + k.w * w.w;
    }
    s = bsum<256>(s);
    if (threadIdx.x == 0) g_u[i] = (1.0f / NDIM) / s;
}

__global__ void sink_colpart_kernel() {
    int col = (blockIdx.x << 8) + threadIdx.x;
    int r0 = blockIdx.y << 7;
    const float* base = g_Kmat + (size_t)r0 * NDIM + col;
    float s0 = 0.f, s1 = 0.f, s2 = 0.f, s3 = 0.f;
#pragma unroll 8
    for (int i = 0; i < 128; i += 4) {
        s0 += base[(size_t)(i + 0) * NDIM] * g_u[r0 + i + 0];
        s1 += base[(size_t)(i + 1) * NDIM] * g_u[r0 + i + 1];
        s2 += base[(size_t)(i + 2) * NDIM] * g_u[r0 + i + 2];
        s3 += base[(size_t)(i + 3) * NDIM] * g_u[r0 + i + 3];
    }
    g_colpart[(blockIdx.y << 12) + col] = (s0 + s1) + (s2 + s3);
}

__global__ void colfin_kernel() {
    int col = (blockIdx.x << 8) + threadIdx.x;
    float s = 0.f;
#pragma unroll
    for (int p = 0; p < 32; p++) s += g_colpart[(p << 12) + col];
    g_v[col] = (1.0f / NDIM) / s;
}

__global__ void gmax0_kernel(float* __restrict__ partials) {
    const int i = blockIdx.x;
    const float invn = 1.0f / NDIM;
    const float ai = g_sg2[i] * invn;
    const float gi = 2.0f * g_rg[i] * invn * invn;
    const float4* sp = (const float4*)g_sr2;
    const float4* rp = (const float4*)g_rr;
    float m = 0.f;
    for (int j = threadIdx.x; j < NDIM / 4; j += 256) {
        float4 s = sp[j], rr = rp[j];
        m = fmaxf(m, fabsf(ai + s.x * invn - gi * rr.x));
        m = fmaxf(m, fabsf(ai + s.y * invn - gi * rr.y));
        m = fmaxf(m, fabsf(ai + s.z * invn - gi * rr.z));
        m = fmaxf(m, fabsf(ai + s.w * invn - gi * rr.w));
    }
    m = bmax<256>(m);
    if (threadIdx.x == 0) partials[i] = m;
}

template<int ITER0>
__global__ void fusedmax_kernel(float* __restrict__ partials) {
    const int i = blockIdx.x;
    const float invcw = (g_scal[0] > 0.f) ? 1.f / g_scal[0] : 1.f;
    const float invg  = (g_scal[1] > 0.f) ? 1.f / g_scal[1] : 1.f;
    const float invn = 1.0f / NDIM;
    const float ai = g_sg2[i] * invn;
    const float gi = 2.0f * g_rg[i] * invn * invn;
    const float4* cwp = (const float4*)(g_CW + (size_t)i * NDIM);
    const float4* cgp = (const float4*)(g_CGW + (size_t)i * NDIM);
    const float4* sp = (const float4*)g_sr2;
    const float4* rp = (const float4*)g_rr;
    float m = -3.402823466e38f;
    for (int j = threadIdx.x; j < NDIM / 4; j += 256) {
        float4 cw = cwp[j], cg;
        if (ITER0) {
            float4 s = sp[j], rr = rp[j];
            cg.x = ai + s.x * invn - gi * rr.x; cg.y = ai + s.y * invn - gi * rr.y;
            cg.z = ai + s.z * invn - gi * rr.z; cg.w = ai + s.w * invn - gi * rr.w;
        } else cg = cgp[j];
        m = fmaxf(m, 0.5f * cw.x * invcw + 0.5f * cg.x * invg);
        m = fmaxf(m, 0.5f * cw.y * invcw + 0.5f * cg.y * invg);
        m = fmaxf(m, 0.5f * cw.z * invcw + 0.5f * cg.z * invg);
        m = fmaxf(m, 0.5f * cw.w * invcw + 0.5f * cg.w * invg);
    }
    m = bmax<256>(m);
    if (threadIdx.x == 0) partials[i] = m;
}

template<int ITER0>
__global__ void kexp_kernel() {
    const int i = blockIdx.x;
    const float invcw = (g_scal[0] > 0.f) ? 1.f / g_scal[0] : 1.f;
    const float invg  = (g_scal[1] > 0.f) ? 1.f / g_scal[1] : 1.f;
    const float cm = g_scal[2];
    const float sc = (cm > 0.f) ? (-1.f / ((cm + 1e-8f) * EPS_R)) : (-1.f / EPS_R);
    const float invn = 1.0f / NDIM;
    const float ai = g_sg2[i] * invn;
    const float gi = 2.0f * g_rg[i] * invn * invn;
    const float4* cwp = (const float4*)(g_CW + (size_t)i * NDIM);
    const float4* cgp = (const float4*)(g_CGW + (size_t)i * NDIM);
    const float4* sp = (const float4*)g_sr2;
    const float4* rp = (const float4*)g_rr;
    float4* kp = (float4*)(g_Kmat + (size_t)i * NDIM);
    for (int j = threadIdx.x; j < NDIM / 4; j += 256) {
        float4 cw = cwp[j], cg;
        if (ITER0) {
            float4 s = sp[j], rr = rp[j];
            cg.x = ai + s.x * invn - gi * rr.x; cg.y = ai + s.y * invn - gi * rr.y;
            cg.z = ai + s.z * invn - gi * rr.z; cg.w = ai + s.w * invn - gi * rr.w;
        } else cg = cgp[j];
        float4 o;
        o.x = __expf((0.5f * cw.x * invcw + 0.5f * cg.x * invg) * sc);
        o.y = __expf((0.5f * cw.y * invcw + 0.5f * cg.y * invg) * sc);
        o.z = __expf((0.5f * cw.z * invcw + 0.5f * cg.z * invg) * sc);
        o.w = __expf((0.5f * cw.w * invcw + 0.5f * cg.w * invg) * sc);
        kp[j] = o;
    }
}

// P = u_i K_ij v_j (S == 1 + O(1e-6) by construction); also emits mu = rowsum(P)
__global__ void pwrite_kernel(float* __restrict__ P) {
    int i = blockIdx.x;
    float ui = g_u[i];
    const float4* kr = (const float4*)(g_Kmat + (size_t)i * NDIM);
    const float4* vv = (const float4*)g_v;
    float4* pr = (float4*)(P + (size_t)i * NDIM);
    float s = 0.f;
    for (int j = threadIdx.x; j < NDIM / 4; j += 256) {
        float4 k = kr[j], w = vv[j];
        float4 o;
        o.x = ui * k.x * w.x; o.y = ui * k.y * w.y; o.z = ui * k.z * w.z; o.w = ui * k.w * w.w;
        pr[j] = o;
        s += o.x + o.y + o.z + o.w;
    }
    s = bsum<256>(s);
    if (threadIdx.x == 0) g_mu[i] = s;
}

__global__ void cfinal_kernel(float* __restrict__ out) {
    size_t stride = (size_t)gridDim.x * blockDim.x;
    const float4* cwp = (const float4*)g_CW;
    const float4* cgp = (const float4*)g_CGW;
    float4* op = (float4*)out;
    for (size_t i = (size_t)blockIdx.x * blockDim.x + threadIdx.x; i < NMTOT / 4; i += stride) {
        float4 cw = cwp[i], cg = cgp[i];
        op[i] = make_float4(0.5f * cw.x + 0.5f * cg.x, 0.5f * cw.y + 0.5f * cg.y,
                            0.5f * cw.z + 0.5f * cg.z, 0.5f * cw.w + 0.5f * cg.w);
    }
}

__global__ void reduce_max_kernel(const float* __restrict__ part, int n, int slot) {
    float m = -3.402823466e38f;
    for (int i = threadIdx.x; i < n; i += 1024) m = fmaxf(m, part[i]);
    m = bmax<1024>(m);
    if (threadIdx.x == 0) g_scal[slot] = m;
}

// ---------------- launch --------------------------------------------------
extern "C" void kernel_launch(void* const* d_in, const int* in_sizes, int n_in,
                              void* d_out, int out_size) {
    const float* fg = (const float*)d_in[0];
    const float* fr = (const float*)d_in[1];
    float* P  = (float*)d_out;
    float* Cf = (float*)d_out + NMTOT;

    float *Dgen, *Dreal, *CW, *CGW, *x2g, *x2r, *sg2, *sr2, *rg, *rr, *part, *v;
    __nv_bfloat16 *Dgh, *Dgl, *Drh, *Drl, *Pth, *Ptl, *Th, *Tl, *Fgh, *Fgl, *Frh, *Frl;
    cudaGetSymbolAddress((void**)&Dgen, g_Dgen);   cudaGetSymbolAddress((void**)&Dreal, g_Dreal);
    cudaGetSymbolAddress((void**)&CW, g_CW);       cudaGetSymbolAddress((void**)&CGW, g_CGW);
    cudaGetSymbolAddress((void**)&x2g, g_x2g);     cudaGetSymbolAddress((void**)&x2r, g_x2r);
    cudaGetSymbolAddress((void**)&sg2, g_sg2);     cudaGetSymbolAddress((void**)&sr2, g_sr2);
    cudaGetSymbolAddress((void**)&rg, g_rg);       cudaGetSymbolAddress((void**)&rr, g_rr);
    cudaGetSymbolAddress((void**)&part, g_part);   cudaGetSymbolAddress((void**)&v, g_v);
    cudaGetSymbolAddress((void**)&Dgh, g_Dg_h);    cudaGetSymbolAddress((void**)&Dgl, g_Dg_l);
    cudaGetSymbolAddress((void**)&Drh, g_Dr_h);    cudaGetSymbolAddress((void**)&Drl, g_Dr_l);
    cudaGetSymbolAddress((void**)&Pth, g_Pt_h);    cudaGetSymbolAddress((void**)&Ptl, g_Pt_l);
    cudaGetSymbolAddress((void**)&Th, g_T_h);      cudaGetSymbolAddress((void**)&Tl, g_T_l);
    cudaGetSymbolAddress((void**)&Fgh, g_Fg_h);    cudaGetSymbolAddress((void**)&Fgl, g_Fg_l);
    cudaGetSymbolAddress((void**)&Frh, g_Fr_h);    cudaGetSymbolAddress((void**)&Frl, g_Fr_l);

    cudaFuncSetAttribute((const void*)mma_gemm_kernel<0, 128, NDIM>, cudaFuncAttributeMaxDynamicSharedMemorySize, SMEM_MM);
    cudaFuncSetAttribute((const void*)mma_gemm_kernel<1, 128, NDIM>, cudaFuncAttributeMaxDynamicSharedMemorySize, SMEM_MM);
    cudaFuncSetAttribute((const void*)mma_gemm_kernel<2, 8, DDIM>,  cudaFuncAttributeMaxDynamicSharedMemorySize, SMEM_MM);
    cudaFuncSetAttribute((const void*)mma_gemm_kernel<3, 8, DDIM>,  cudaFuncAttributeMaxDynamicSharedMemorySize, SMEM_MM);

    const dim3 gg(32, 32);
    const dim3 gcol(16, 32);
    const dim3 gtr(128, 128);
    const dim3 btr(32, 8);

    // feature norms + splits, cdist via tensor cores
    sqnorm_kernel<<<NDIM, 64>>>(fg, x2g);
    sqnorm_kernel<<<NDIM, 64>>>(fr, x2r);
    split2_kernel<<<1024, 256>>>(fg, Fgh, Fgl, (size_t)NDIM * DDIM / 2);
    split2_kernel<<<1024, 256>>>(fr, Frh, Frl, (size_t)NDIM * DDIM / 2);
    mma_gemm_kernel<2, 8, DDIM><<<gg, 256, SMEM_MM>>>(Fgh, Fgl, Fgh, Fgl, nullptr, nullptr, Dgen, nullptr, x2g, x2g);
    mma_gemm_kernel<2, 8, DDIM><<<gg, 256, SMEM_MM>>>(Frh, Frl, Frh, Frl, nullptr, nullptr, Dreal, nullptr, x2r, x2r);
    mma_gemm_kernel<3, 8, DDIM><<<gg, 256, SMEM_MM>>>(Fgh, Fgl, Frh, Frl, nullptr, nullptr, CW, part, x2g, x2r);
    reduce_max_kernel<<<1, 1024>>>(part, 1024, 0);           // cwmax

    row_sumsq_kernel<<<NDIM, 256>>>(Dgen, sg2);
    row_sumsq_kernel<<<NDIM, 256>>>(Dreal, sr2);
    row_sum_kernel<<<NDIM, 256>>>(Dgen, rg);
    row_sum_kernel<<<NDIM, 256>>>(Dreal, rr);                // symmetric -> colsum
    split2_kernel<<<4096, 256>>>(Dgen, Dgh, Dgl, NMTOT / 2);
    split2_kernel<<<4096, 256>>>(Dreal, Drh, Drl, NMTOT / 2);  // symmetric -> B^T == B

    for (int it = 0; it < N_FGW; it++) {
        if (it == 0) {
            // coupling = a b^T is rank-1: closed-form CGW0
            gmax0_kernel<<<NDIM, 256>>>(part);
            reduce_max_kernel<<<1, 1024>>>(part, 4096, 1);   // gmax
            fusedmax_kernel<1><<<NDIM, 256>>>(part);
            reduce_max_kernel<<<1, 1024>>>(part, 4096, 2);   // cmax
            kexp_kernel<1><<<NDIM, 256>>>();
        } else {
            // mu from previous pwrite; nu == 1/NDIM (exact col marginal)
            transpose_split2_kernel<<<gtr, btr>>>(P, Pth, Ptl);
            mma_gemm_kernel<0, 128, NDIM><<<gg, 256, SMEM_MM>>>(Dgh, Dgl, Pth, Ptl, Th, Tl, nullptr, nullptr, nullptr, nullptr);
            mma_gemm_kernel<1, 128, NDIM><<<gg, 256, SMEM_MM>>>(Th, Tl, Drh, Drl, nullptr, nullptr, CGW, part, nullptr, nullptr);
            reduce_max_kernel<<<1, 1024>>>(part, 1024, 1);   // gmax
            fusedmax_kernel<0><<<NDIM, 256>>>(part);
            reduce_max_kernel<<<1, 1024>>>(part, 4096, 2);   // cmax
            kexp_kernel<0><<<NDIM, 256>>>();
        }
        // Sinkhorn (launch-based, graph-replayed: launches are cheap)
        fill_kernel<<<16, 256>>>(v, 1.0f, (size_t)NDIM);
        for (int s = 0; s < N_SINK; s++) {
            sink_row_kernel<<<NDIM, 256>>>();
            sink_colpart_kernel<<<gcol, 256>>>();
            colfin_kernel<<<16, 256>>>();
        }
        pwrite_kernel<<<NDIM, 256>>>(P);                     // P + mu in one pass
    }
    cfinal_kernel<<<4096, 256>>>(Cf);
}

// round 15
// speedup vs baseline: 1.3064x; 1.0150x over previous
#include <cuda_runtime.h>
#include <cuda_bf16.h>
#include <cstdint>
#include <cstddef>

#define NDIM 4096
#define DDIM 256
#define NMTOT ((size_t)NDIM * (size_t)NDIM)
#define EPS_R 0.05f
#define N_SINK 30
#define N_FGW 5

// ---------------- device scratch ----------------
__device__ float g_Dgen [NDIM * NDIM];
__device__ float g_Dreal[NDIM * NDIM];
__device__ float g_CW   [NDIM * NDIM];
__device__ float g_CGW  [NDIM * NDIM];
__device__ float g_Kmat [NDIM * NDIM];
__device__ __nv_bfloat16 g_Dg_h[NDIM * NDIM], g_Dg_l[NDIM * NDIM];
__device__ __nv_bfloat16 g_Dr_h[NDIM * NDIM], g_Dr_l[NDIM * NDIM];
__device__ __nv_bfloat16 g_P_h [NDIM * NDIM], g_P_l [NDIM * NDIM];   // P split, row-major
__device__ __nv_bfloat16 g_W_h [NDIM * NDIM], g_W_l [NDIM * NDIM];   // W = Dreal*P^T
__device__ __nv_bfloat16 g_Fg_h[NDIM * DDIM], g_Fg_l[NDIM * DDIM];
__device__ __nv_bfloat16 g_Fr_h[NDIM * DDIM], g_Fr_l[NDIM * DDIM];
__device__ float g_x2g[NDIM], g_x2r[NDIM];
__device__ float g_sg2[NDIM], g_sr2[NDIM];
__device__ float g_rg [NDIM], g_rr [NDIM];
__device__ float g_mu [NDIM];
__device__ float g_u  [NDIM], g_v  [NDIM];
__device__ float g_colpart[32 * NDIM];
__device__ float g_part[8192];
__device__ float g_scal[8];   // 0:cwmax 1:gmax 2:cmax

// ---------------- helpers ----------------
__device__ __forceinline__ uint32_t pack2(float f0, float f1) {
    __nv_bfloat162 p; p.x = __float2bfloat16(f0); p.y = __float2bfloat16(f1);
    return *reinterpret_cast<uint32_t*>(&p);
}
__device__ __forceinline__ void ldm_x4(uint32_t* r, uint32_t a) {
    asm volatile("ldmatrix.sync.aligned.m8n8.x4.shared.b16 {%0,%1,%2,%3}, [%4];"
        : "=r"(r[0]), "=r"(r[1]), "=r"(r[2]), "=r"(r[3]) : "r"(a));
}
__device__ __forceinline__ void mma16816(float* c, const uint32_t* a, const uint32_t* b) {
    asm volatile("mma.sync.aligned.m16n8k16.row.col.f32.bf16.bf16.f32 "
        "{%0,%1,%2,%3}, {%4,%5,%6,%7}, {%8,%9}, {%0,%1,%2,%3};"
        : "+f"(c[0]), "+f"(c[1]), "+f"(c[2]), "+f"(c[3])
        : "r"(a[0]), "r"(a[1]), "r"(a[2]), "r"(a[3]), "r"(b[0]), "r"(b[1]));
}
__device__ __forceinline__ uint32_t smem_u32(const void* p) {
    uint32_t a;
    asm("{ .reg .u64 t; cvta.to.shared.u64 t, %1; cvt.u32.u64 %0, t; }" : "=r"(a) : "l"(p));
    return a;
}
__device__ __forceinline__ void split2(float x, __nv_bfloat16& h, __nv_bfloat16& l) {
    h = __float2bfloat16(x);
    l = __float2bfloat16(x - __bfloat162float(h));
}
#define CP16(dst, src) asm volatile("cp.async.cg.shared.global [%0], [%1], 16;" :: "r"(dst), "l"(src) : "memory")
#define CPC() asm volatile("cp.async.commit_group;" ::: "memory")
#define CPW(n) asm volatile("cp.async.wait_group %0;" :: "n"(n) : "memory")

// ---------------- reductions ----------------
template<int BS>
__device__ __forceinline__ float bsum(float v) {
    static __shared__ float sh[BS];
    int t = threadIdx.x;
    sh[t] = v; __syncthreads();
#pragma unroll
    for (int s = BS / 2; s >= 64; s >>= 1) { if (t < s) sh[t] += sh[t + s]; __syncthreads(); }
    float x = 0.f;
    if (t < 32) {
        x = sh[t] + sh[t + 32];
#pragma unroll
        for (int o = 16; o; o >>= 1) x += __shfl_down_sync(0xffffffffu, x, o);
    }
    return x;
}
template<int BS>
__device__ __forceinline__ float bmax(float v) {
    static __shared__ float sh[BS];
    int t = threadIdx.x;
    sh[t] = v; __syncthreads();
#pragma unroll
    for (int s = BS / 2; s >= 64; s >>= 1) { if (t < s) sh[t] = fmaxf(sh[t], sh[t + s]); __syncthreads(); }
    float x = -3.402823466e38f;
    if (t < 32) {
        x = fmaxf(sh[t], sh[t + 32]);
#pragma unroll
        for (int o = 16; o; o >>= 1) x = fmaxf(x, __shfl_down_sync(0xffffffffu, x, o));
    }
    return x;
}

// ---------------- 3-term split bf16 GEMM, two-level accumulation ----------
// C[m,n] = sum_k A[m,k]*B[n,k] (both operands K-major row-major).
// MODE 0: emit C re-split bf16 (W). 1: CGW epilogue + gmax (nu==1/NDIM).
// MODE 4: MODE 1 + also write Cfin = 0.5*CW + 0.5*CGW (fused cfinal).
// MODE 2: cdist sqrt epilogue (fp32). 3: CW relu epilogue + max.
#define STG_T 10240               // one tile: 128 rows * 80B (64B data + 16B pad)
#define STG_S (4 * STG_T)         // Ah,Al,Bh,Bl = 40960
#define SMEM_MM (3 * STG_S)       // 3 stages = 122880
#define BKT 32

template<int MODE, int NT, int LDK>
__global__ void __launch_bounds__(256, 1)
mma_gemm_kernel(const __nv_bfloat16* __restrict__ Ah_, const __nv_bfloat16* __restrict__ Al_,
                const __nv_bfloat16* __restrict__ Bh_, const __nv_bfloat16* __restrict__ Bl_,
                __nv_bfloat16* __restrict__ Oh, __nv_bfloat16* __restrict__ Ol,
                float* __restrict__ Cout, float* __restrict__ partials,
                const float* __restrict__ vx, const float* __restrict__ vy,
                float* __restrict__ Cfin)
{
    extern __shared__ char smem[];
    const uint32_t sb = smem_u32(smem);
    const int tid = threadIdx.x, warp = tid >> 5, lane = tid & 31;
    const int bm = blockIdx.y << 7, bn = blockIdx.x << 7;
    const int wm = (warp >> 2) << 6, wn = (warp & 3) << 5;  // warp tile 64x32

    const char* srcs[4] = {
        (const char*)(Ah_ + (size_t)bm * LDK), (const char*)(Al_ + (size_t)bm * LDK),
        (const char*)(Bh_ + (size_t)bn * LDK), (const char*)(Bl_ + (size_t)bn * LDK) };

    auto load_stage = [&](int slot, int kt) {
        const uint32_t sbase = sb + slot * STG_S;
        const size_t ko = (size_t)kt * (BKT * 2);
#pragma unroll
        for (int i = 0; i < 8; i++) {
            const int tile = i >> 1;
            const int wc = ((i & 1) << 8) + tid;        // 0..511 within tile
            const int row = wc >> 2, cc = wc & 3;
            uint32_t dst = sbase + tile * STG_T + row * 80 + (cc << 4);
            const char* src = srcs[tile] + (size_t)row * (LDK * 2) + ko + (cc << 4);
            CP16(dst, src);
        }
    };

    float acc[4][4][4], accS[4][4][4];
#pragma unroll
    for (int a = 0; a < 4; a++)
#pragma unroll
        for (int b = 0; b < 4; b++)
#pragma unroll
            for (int c = 0; c < 4; c++) { acc[a][b][c] = 0.f; accS[a][b][c] = 0.f; }

    load_stage(0, 0); CPC();
    load_stage(1, 1); CPC();

    const int grp = lane >> 3, l8 = lane & 7;

    for (int kt = 0; kt < NT; kt++) {
        CPW(1);
        __syncthreads();
        if (kt + 2 < NT) load_stage((kt + 2) % 3, kt + 2);
        CPC();
        const uint32_t stb = sb + (kt % 3) * STG_S;
#pragma unroll
        for (int ks = 0; ks < 2; ks++) {
            uint32_t ah[4][4], al[4][4], bh[4][2], bl[4][2], t[4];
            const uint32_t acol = (ks << 5) + ((grp >> 1) << 4);
#pragma unroll
            for (int mi = 0; mi < 4; mi++) {
                uint32_t ro = (uint32_t)(wm + (mi << 4) + ((grp & 1) << 3) + l8) * 80 + acol;
                ldm_x4(ah[mi], stb + 0 * STG_T + ro);
                ldm_x4(al[mi], stb + 1 * STG_T + ro);
            }
            const uint32_t bcol = (ks << 5) + ((grp & 1) << 4);
#pragma unroll
            for (int np = 0; np < 2; np++) {
                uint32_t ro = (uint32_t)(wn + (np << 4) + ((grp >> 1) << 3) + l8) * 80 + bcol;
                ldm_x4(t, stb + 2 * STG_T + ro);
                bh[2 * np][0] = t[0]; bh[2 * np][1] = t[1];
                bh[2 * np + 1][0] = t[2]; bh[2 * np + 1][1] = t[3];
                ldm_x4(t, stb + 3 * STG_T + ro);
                bl[2 * np][0] = t[0]; bl[2 * np][1] = t[1];
                bl[2 * np + 1][0] = t[2]; bl[2 * np + 1][1] = t[3];
            }
#pragma unroll
            for (int mi = 0; mi < 4; mi++)
#pragma unroll
                for (int ni = 0; ni < 4; ni++) {
                    mma16816(acc[mi][ni], ah[mi], bh[ni]);
                    mma16816(acc[mi][ni], ah[mi], bl[ni]);
                    mma16816(acc[mi][ni], al[mi], bh[ni]);
                }
        }
        if ((kt & 15) == 15 || kt == NT - 1) {   // pairwise flush (noise control)
#pragma unroll
            for (int a = 0; a < 4; a++)
#pragma unroll
                for (int b = 0; b < 4; b++)
#pragma unroll
                    for (int c = 0; c < 4; c++) { accS[a][b][c] += acc[a][b][c]; acc[a][b][c] = 0.f; }
        }
    }

    const float invn = 1.0f / NDIM;
    float lmax = 0.f;
#pragma unroll
    for (int mi = 0; mi < 4; mi++) {
        const int r1 = bm + wm + (mi << 4) + (lane >> 2);
        const int r2 = r1 + 8;
        float pA0 = 0.f, pA1 = 0.f, pB0 = 0.f, pB1 = 0.f;
        if (MODE == 1 || MODE == 4) { pA0 = g_sg2[r1]; pA1 = g_mu[r1]; pB0 = g_sg2[r2]; pB1 = g_mu[r2]; }
        if (MODE == 2 || MODE == 3) { pA0 = vx[r1]; pB0 = vx[r2]; }
#pragma unroll
        for (int ni = 0; ni < 4; ni++) {
            const int n1 = bn + wn + (ni << 3) + ((lane & 3) << 1);
            const float c0 = accS[mi][ni][0], c1 = accS[mi][ni][1];
            const float c2 = accS[mi][ni][2], c3 = accS[mi][ni][3];
            if (MODE == 0) {
                __nv_bfloat16 h0, l0, h1, l1;
                split2(c0, h0, l0); split2(c1, h1, l1);
                __nv_bfloat162 ll01{l0, l1};
                *(uint32_t*)(Oh + (size_t)r1 * NDIM + n1) = pack2(c0, c1);
                *(uint32_t*)(Ol + (size_t)r1 * NDIM + n1) = *(uint32_t*)&ll01;
                __nv_bfloat16 h2, l2, h3, l3;
                split2(c2, h2, l2); split2(c3, h3, l3);
                __nv_bfloat162 ll23{l2, l3};
                *(uint32_t*)(Oh + (size_t)r2 * NDIM + n1) = pack2(c2, c3);
                *(uint32_t*)(Ol + (size_t)r2 * NDIM + n1) = *(uint32_t*)&ll23;
            } else if (MODE == 1 || MODE == 4) {
                const float s1 = g_sr2[n1], s2 = g_sr2[n1 + 1];
                float v0 = pA0 * invn + pA1 * s1 - 2.f * c0;
                float v1 = pA0 * invn + pA1 * s2 - 2.f * c1;
                float v2 = pB0 * invn + pB1 * s1 - 2.f * c2;
                float v3 = pB0 * invn + pB1 * s2 - 2.f * c3;
                lmax = fmaxf(fmaxf(lmax, fabsf(v0)), fmaxf(fabsf(v1), fmaxf(fabsf(v2), fabsf(v3))));
                *(float2*)(Cout + (size_t)r1 * NDIM + n1) = make_float2(v0, v1);
                *(float2*)(Cout + (size_t)r2 * NDIM + n1) = make_float2(v2, v3);
                if (MODE == 4) {   // fused C_final = 0.5*CW + 0.5*CGW
                    float2 w1 = *(const float2*)(g_CW + (size_t)r1 * NDIM + n1);
                    float2 w2 = *(const float2*)(g_CW + (size_t)r2 * NDIM + n1);
                    *(float2*)(Cfin + (size_t)r1 * NDIM + n1) =
                        make_float2(0.5f * w1.x + 0.5f * v0, 0.5f * w1.y + 0.5f * v1);
                    *(float2*)(Cfin + (size_t)r2 * NDIM + n1) =
                        make_float2(0.5f * w2.x + 0.5f * v2, 0.5f * w2.y + 0.5f * v3);
                }
            } else {
                const float q1 = vy[n1], q2 = vy[n1 + 1];
                float d0 = fmaxf(pA0 + q1 - 2.f * c0, 0.f);
                float d1 = fmaxf(pA0 + q2 - 2.f * c1, 0.f);
                float d2 = fmaxf(pB0 + q1 - 2.f * c2, 0.f);
                float d3 = fmaxf(pB0 + q2 - 2.f * c3, 0.f);
                float v0, v1, v2, v3;
                if (MODE == 2) {
                    v0 = (d0 > 0.f) ? sqrtf(d0) : 0.f; v1 = (d1 > 0.f) ? sqrtf(d1) : 0.f;
                    v2 = (d2 > 0.f) ? sqrtf(d2) : 0.f; v3 = (d3 > 0.f) ? sqrtf(d3) : 0.f;
                } else {
                    v0 = d0; v1 = d1; v2 = d2; v3 = d3;
                    lmax = fmaxf(fmaxf(lmax, d0), fmaxf(d1, fmaxf(d2, d3)));
                }
                *(float2*)(Cout + (size_t)r1 * NDIM + n1) = make_float2(v0, v1);
                *(float2*)(Cout + (size_t)r2 * NDIM + n1) = make_float2(v2, v3);
            }
        }
    }
    if (MODE == 1 || MODE == 3 || MODE == 4) {
        float mm = bmax<256>(lmax);
        if (tid == 0) partials[blockIdx.y * gridDim.x + blockIdx.x] = mm;
    }
}

// ---------------- small kernels ----------------
__global__ void sqnorm_kernel(const float* __restrict__ X, float* __restrict__ out) {
    int i = blockIdx.x;
    float4 a = ((const float4*)(X + (size_t)i * DDIM))[threadIdx.x];
    float s = a.x * a.x + a.y * a.y + a.z * a.z + a.w * a.w;
    s = bsum<64>(s);
    if (threadIdx.x == 0) out[i] = s;
}

__global__ void fill_kernel(float* __restrict__ p, float val, size_t n) {
    size_t stride = (size_t)gridDim.x * blockDim.x;
    for (size_t i = (size_t)blockIdx.x * blockDim.x + threadIdx.x; i < n; i += stride) p[i] = val;
}

__global__ void row_sum_kernel(const float* __restrict__ M, float* __restrict__ out) {
    int i = blockIdx.x;
    const float4* rp = (const float4*)(M + (size_t)i * NDIM);
    float s = 0.f;
    for (int j = threadIdx.x; j < NDIM / 4; j += 256) { float4 a = rp[j]; s += a.x + a.y + a.z + a.w; }
    s = bsum<256>(s);
    if (threadIdx.x == 0) out[i] = s;
}

__global__ void row_sumsq_kernel(const float* __restrict__ M, float* __restrict__ out) {
    int i = blockIdx.x;
    const float4* rp = (const float4*)(M + (size_t)i * NDIM);
    float s = 0.f;
    for (int j = threadIdx.x; j < NDIM / 4; j += 256) {
        float4 a = rp[j];
        s += a.x * a.x + a.y * a.y + a.z * a.z + a.w * a.w;
    }
    s = bsum<256>(s);
    if (threadIdx.x == 0) out[i] = s;
}

// fp32 -> bf16 hi/lo, float4-wide
__global__ void split2_kernel(const float* __restrict__ src, __nv_bfloat16* __restrict__ dh,
                              __nv_bfloat16* __restrict__ dl, size_t n4) {
    size_t stride = (size_t)gridDim.x * blockDim.x;
    const float4* sp = (const float4*)src;
    uint2* hp = (uint2*)dh; uint2* lp = (uint2*)dl;
    for (size_t i = (size_t)blockIdx.x * blockDim.x + threadIdx.x; i < n4; i += stride) {
        float4 f = sp[i];
        __nv_bfloat16 h0, l0, h1, l1, h2, l2, h3, l3;
        split2(f.x, h0, l0); split2(f.y, h1, l1);
        split2(f.z, h2, l2); split2(f.w, h3, l3);
        __nv_bfloat162 hA{h0, h1}, hB{h2, h3}, lA{l0, l1}, lB{l2, l3};
        hp[i] = make_uint2(*(uint32_t*)&hA, *(uint32_t*)&hB);
        lp[i] = make_uint2(*(uint32_t*)&lA, *(uint32_t*)&lB);
    }
}

// Sinkhorn kernels (launch-based, proven)
__global__ void sink_row_kernel() {
    int i = blockIdx.x;
    const float4* kr = (const float4*)(g_Kmat + (size_t)i * NDIM);
    const float4* vv = (const float4*)g_v;
    float s = 0.f;
    for (int j = threadIdx.x; j < NDIM / 4; j += 256) {
        float4 k = kr[j], w = vv[j];
        s += k.x * w.x + k.y * w.y + k.z * w.z + k.w * w.w;
    }
    s = bsum<256>(s);
    if (threadIdx.x == 0) g_u[i] = (1.0f / NDIM) / s;
}

__global__ void sink_colpart_kernel() {
    int col = (blockIdx.x << 8) + threadIdx.x;
    int r0 = blockIdx.y << 7;
    const float* base = g_Kmat + (size_t)r0 * NDIM + col;
    float s0 = 0.f, s1 = 0.f, s2 = 0.f, s3 = 0.f;
#pragma unroll 8
    for (int i = 0; i < 128; i += 4) {
        s0 += base[(size_t)(i + 0) * NDIM] * g_u[r0 + i + 0];
        s1 += base[(size_t)(i + 1) * NDIM] * g_u[r0 + i + 1];
        s2 += base[(size_t)(i + 2) * NDIM] * g_u[r0 + i + 2];
        s3 += base[(size_t)(i + 3) * NDIM] * g_u[r0 + i + 3];
    }
    g_colpart[(blockIdx.y << 12) + col] = (s0 + s1) + (s2 + s3);
}

__global__ void colfin_kernel() {
    int col = (blockIdx.x << 8) + threadIdx.x;
    float s = 0.f;
#pragma unroll
    for (int p = 0; p < 32; p++) s += g_colpart[(p << 12) + col];
    g_v[col] = (1.0f / NDIM) / s;
}

__global__ void gmax0_kernel(float* __restrict__ partials) {
    const int i = blockIdx.x;
    const float invn = 1.0f / NDIM;
    const float ai = g_sg2[i] * invn;
    const float gi = 2.0f * g_rg[i] * invn * invn;
    const float4* sp = (const float4*)g_sr2;
    const float4* rp = (const float4*)g_rr;
    float m = 0.f;
    for (int j = threadIdx.x; j < NDIM / 4; j += 256) {
        float4 s = sp[j], rr = rp[j];
        m = fmaxf(m, fabsf(ai + s.x * invn - gi * rr.x));
        m = fmaxf(m, fabsf(ai + s.y * invn - gi * rr.y));
        m = fmaxf(m, fabsf(ai + s.z * invn - gi * rr.z));
        m = fmaxf(m, fabsf(ai + s.w * invn - gi * rr.w));
    }
    m = bmax<256>(m);
    if (threadIdx.x == 0) partials[i] = m;
}

template<int ITER0>
__global__ void fusedmax_kernel(float* __restrict__ partials) {
    const int i = blockIdx.x;
    const float invcw = (g_scal[0] > 0.f) ? 1.f / g_scal[0] : 1.f;
    const float invg  = (g_scal[1] > 0.f) ? 1.f / g_scal[1] : 1.f;
    const float invn = 1.0f / NDIM;
    const float ai = g_sg2[i] * invn;
    const float gi = 2.0f * g_rg[i] * invn * invn;
    const float4* cwp = (const float4*)(g_CW + (size_t)i * NDIM);
    const float4* cgp = (const float4*)(g_CGW + (size_t)i * NDIM);
    const float4* sp = (const float4*)g_sr2;
    const float4* rp = (const float4*)g_rr;
    float m = -3.402823466e38f;
    for (int j = threadIdx.x; j < NDIM / 4; j += 256) {
        float4 cw = cwp[j], cg;
        if (ITER0) {
            float4 s = sp[j], rr = rp[j];
            cg.x = ai + s.x * invn - gi * rr.x; cg.y = ai + s.y * invn - gi * rr.y;
            cg.z = ai + s.z * invn - gi * rr.z; cg.w = ai + s.w * invn - gi * rr.w;
        } else cg = cgp[j];
        m = fmaxf(m, 0.5f * cw.x * invcw + 0.5f * cg.x * invg);
        m = fmaxf(m, 0.5f * cw.y * invcw + 0.5f * cg.y * invg);
        m = fmaxf(m, 0.5f * cw.z * invcw + 0.5f * cg.z * invg);
        m = fmaxf(m, 0.5f * cw.w * invcw + 0.5f * cg.w * invg);
    }
    m = bmax<256>(m);
    if (threadIdx.x == 0) partials[i] = m;
}

template<int ITER0>
__global__ void kexp_kernel() {
    const int i = blockIdx.x;
    const float invcw = (g_scal[0] > 0.f) ? 1.f / g_scal[0] : 1.f;
    const float invg  = (g_scal[1] > 0.f) ? 1.f / g_scal[1] : 1.f;
    const float cm = g_scal[2];
    const float sc = (cm > 0.f) ? (-1.f / ((cm + 1e-8f) * EPS_R)) : (-1.f / EPS_R);
    const float invn = 1.0f / NDIM;
    const float ai = g_sg2[i] * invn;
    const float gi = 2.0f * g_rg[i] * invn * invn;
    const float4* cwp = (const float4*)(g_CW + (size_t)i * NDIM);
    const float4* cgp = (const float4*)(g_CGW + (size_t)i * NDIM);
    const float4* sp = (const float4*)g_sr2;
    const float4* rp = (const float4*)g_rr;
    float4* kp = (float4*)(g_Kmat + (size_t)i * NDIM);
    for (int j = threadIdx.x; j < NDIM / 4; j += 256) {
        float4 cw = cwp[j], cg;
        if (ITER0) {
            float4 s = sp[j], rr = rp[j];
            cg.x = ai + s.x * invn - gi * rr.x; cg.y = ai + s.y * invn - gi * rr.y;
            cg.z = ai + s.z * invn - gi * rr.z; cg.w = ai + s.w * invn - gi * rr.w;
        } else cg = cgp[j];
        float4 o;
        o.x = __expf((0.5f * cw.x * invcw + 0.5f * cg.x * invg) * sc);
        o.y = __expf((0.5f * cw.y * invcw + 0.5f * cg.y * invg) * sc);
        o.z = __expf((0.5f * cw.z * invcw + 0.5f * cg.z * invg) * sc);
        o.w = __expf((0.5f * cw.w * invcw + 0.5f * cg.w * invg) * sc);
        kp[j] = o;
    }
}

// P = u_i K_ij v_j (S == 1 + O(1e-6) by construction).
// FINAL=0: emit bf16 split of P (GEMM operand) + mu. FINAL=1: emit fp32 P.
template<int FINAL>
__global__ void pwrite_kernel(float* __restrict__ P,
                              __nv_bfloat16* __restrict__ Ph, __nv_bfloat16* __restrict__ Pl) {
    int i = blockIdx.x;
    float ui = g_u[i];
    const float4* kr = (const float4*)(g_Kmat + (size_t)i * NDIM);
    const float4* vv = (const float4*)g_v;
    float4* pr = (float4*)(P + (size_t)i * NDIM);
    uint2* hp = (uint2*)(Ph + (size_t)i * NDIM);
    uint2* lp = (uint2*)(Pl + (size_t)i * NDIM);
    float s = 0.f;
    for (int j = threadIdx.x; j < NDIM / 4; j += 256) {
        float4 k = kr[j], w = vv[j];
        float4 o;
        o.x = ui * k.x * w.x; o.y = ui * k.y * w.y; o.z = ui * k.z * w.z; o.w = ui * k.w * w.w;
        if (FINAL) {
            pr[j] = o;
        } else {
            __nv_bfloat16 h0, l0, h1, l1, h2, l2, h3, l3;
            split2(o.x, h0, l0); split2(o.y, h1, l1);
            split2(o.z, h2, l2); split2(o.w, h3, l3);
            __nv_bfloat162 hA{h0, h1}, hB{h2, h3}, lA{l0, l1}, lB{l2, l3};
            hp[j] = make_uint2(*(uint32_t*)&hA, *(uint32_t*)&hB);
            lp[j] = make_uint2(*(uint32_t*)&lA, *(uint32_t*)&lB);
        }
        s += o.x + o.y + o.z + o.w;
    }
    s = bsum<256>(s);
    if (threadIdx.x == 0) g_mu[i] = s;
}

__global__ void reduce_max_kernel(const float* __restrict__ part, int n, int slot) {
    float m = -3.402823466e38f;
    for (int i = threadIdx.x; i < n; i += 1024) m = fmaxf(m, part[i]);
    m = bmax<1024>(m);
    if (threadIdx.x == 0) g_scal[slot] = m;
}

// ---------------- launch --------------------------------------------------
extern "C" void kernel_launch(void* const* d_in, const int* in_sizes, int n_in,
                              void* d_out, int out_size) {
    const float* fg = (const float*)d_in[0];
    const float* fr = (const float*)d_in[1];
    float* P  = (float*)d_out;
    float* Cf = (float*)d_out + NMTOT;

    float *Dgen, *Dreal, *CW, *CGW, *x2g, *x2r, *sg2, *sr2, *rg, *rr, *part, *v;
    __nv_bfloat16 *Dgh, *Dgl, *Drh, *Drl, *Ph, *Pl, *Wh, *Wl, *Fgh, *Fgl, *Frh, *Frl;
    cudaGetSymbolAddress((void**)&Dgen, g_Dgen);   cudaGetSymbolAddress((void**)&Dreal, g_Dreal);
    cudaGetSymbolAddress((void**)&CW, g_CW);       cudaGetSymbolAddress((void**)&CGW, g_CGW);
    cudaGetSymbolAddress((void**)&x2g, g_x2g);     cudaGetSymbolAddress((void**)&x2r, g_x2r);
    cudaGetSymbolAddress((void**)&sg2, g_sg2);     cudaGetSymbolAddress((void**)&sr2, g_sr2);
    cudaGetSymbolAddress((void**)&rg, g_rg);       cudaGetSymbolAddress((void**)&rr, g_rr);
    cudaGetSymbolAddress((void**)&part, g_part);   cudaGetSymbolAddress((void**)&v, g_v);
    cudaGetSymbolAddress((void**)&Dgh, g_Dg_h);    cudaGetSymbolAddress((void**)&Dgl, g_Dg_l);
    cudaGetSymbolAddress((void**)&Drh, g_Dr_h);    cudaGetSymbolAddress((void**)&Drl, g_Dr_l);
    cudaGetSymbolAddress((void**)&Ph, g_P_h);      cudaGetSymbolAddress((void**)&Pl, g_P_l);
    cudaGetSymbolAddress((void**)&Wh, g_W_h);      cudaGetSymbolAddress((void**)&Wl, g_W_l);
    cudaGetSymbolAddress((void**)&Fgh, g_Fg_h);    cudaGetSymbolAddress((void**)&Fgl, g_Fg_l);
    cudaGetSymbolAddress((void**)&Frh, g_Fr_h);    cudaGetSymbolAddress((void**)&Frl, g_Fr_l);

    cudaFuncSetAttribute((const void*)mma_gemm_kernel<0, 128, NDIM>, cudaFuncAttributeMaxDynamicSharedMemorySize, SMEM_MM);
    cudaFuncSetAttribute((const void*)mma_gemm_kernel<1, 128, NDIM>, cudaFuncAttributeMaxDynamicSharedMemorySize, SMEM_MM);
    cudaFuncSetAttribute((const void*)mma_gemm_kernel<4, 128, NDIM>, cudaFuncAttributeMaxDynamicSharedMemorySize, SMEM_MM);
    cudaFuncSetAttribute((const void*)mma_gemm_kernel<2, 8, DDIM>,  cudaFuncAttributeMaxDynamicSharedMemorySize, SMEM_MM);
    cudaFuncSetAttribute((const void*)mma_gemm_kernel<3, 8, DDIM>,  cudaFuncAttributeMaxDynamicSharedMemorySize, SMEM_MM);

    const dim3 gg(32, 32);
    const dim3 gcol(16, 32);

    // feature norms + splits, cdist via tensor cores
    sqnorm_kernel<<<NDIM, 64>>>(fg, x2g);
    sqnorm_kernel<<<NDIM, 64>>>(fr, x2r);
    split2_kernel<<<512, 256>>>(fg, Fgh, Fgl, (size_t)NDIM * DDIM / 4);
    split2_kernel<<<512, 256>>>(fr, Frh, Frl, (size_t)NDIM * DDIM / 4);
    mma_gemm_kernel<2, 8, DDIM><<<gg, 256, SMEM_MM>>>(Fgh, Fgl, Fgh, Fgl, nullptr, nullptr, Dgen, nullptr, x2g, x2g, nullptr);
    mma_gemm_kernel<2, 8, DDIM><<<gg, 256, SMEM_MM>>>(Frh, Frl, Frh, Frl, nullptr, nullptr, Dreal, nullptr, x2r, x2r, nullptr);
    mma_gemm_kernel<3, 8, DDIM><<<gg, 256, SMEM_MM>>>(Fgh, Fgl, Frh, Frl, nullptr, nullptr, CW, part, x2g, x2r, nullptr);
    reduce_max_kernel<<<1, 1024>>>(part, 1024, 0);           // cwmax

    row_sumsq_kernel<<<NDIM, 256>>>(Dgen, sg2);
    row_sumsq_kernel<<<NDIM, 256>>>(Dreal, sr2);
    row_sum_kernel<<<NDIM, 256>>>(Dgen, rg);
    row_sum_kernel<<<NDIM, 256>>>(Dreal, rr);                // symmetric -> colsum
    split2_kernel<<<4096, 256>>>(Dgen, Dgh, Dgl, NMTOT / 4);
    split2_kernel<<<4096, 256>>>(Dreal, Drh, Drl, NMTOT / 4);  // symmetric -> B^T == B

    for (int it = 0; it < N_FGW; it++) {
        if (it == 0) {
            // coupling = a b^T is rank-1: closed-form CGW0
            gmax0_kernel<<<NDIM, 256>>>(part);
            reduce_max_kernel<<<1, 1024>>>(part, 4096, 1);   // gmax
            fusedmax_kernel<1><<<NDIM, 256>>>(part);
            reduce_max_kernel<<<1, 1024>>>(part, 4096, 2);   // cmax
            kexp_kernel<1><<<NDIM, 256>>>();
        } else {
            // no transpose: W = Dreal*P^T (B = P row-major); CGW = Dgen*W^T
            mma_gemm_kernel<0, 128, NDIM><<<gg, 256, SMEM_MM>>>(Drh, Drl, Ph, Pl, Wh, Wl, nullptr, nullptr, nullptr, nullptr, nullptr);
            if (it == N_FGW - 1)
                mma_gemm_kernel<4, 128, NDIM><<<gg, 256, SMEM_MM>>>(Dgh, Dgl, Wh, Wl, nullptr, nullptr, CGW, part, nullptr, nullptr, Cf);
            else
                mma_gemm_kernel<1, 128, NDIM><<<gg, 256, SMEM_MM>>>(Dgh, Dgl, Wh, Wl, nullptr, nullptr, CGW, part, nullptr, nullptr, nullptr);
            reduce_max_kernel<<<1, 1024>>>(part, 1024, 1);   // gmax
            fusedmax_kernel<0><<<NDIM, 256>>>(part);
            reduce_max_kernel<<<1, 1024>>>(part, 4096, 2);   // cmax
            kexp_kernel<0><<<NDIM, 256>>>();
        }
        // Sinkhorn (launch-based, graph-replayed)
        fill_kernel<<<16, 256>>>(v, 1.0f, (size_t)NDIM);
        for (int s = 0; s < N_SINK; s++) {
            sink_row_kernel<<<NDIM, 256>>>();
            sink_colpart_kernel<<<gcol, 256>>>();
            colfin_kernel<<<16, 256>>>();
        }
        if (it == N_FGW - 1) pwrite_kernel<1><<<NDIM, 256>>>(P, Ph, Pl);  // fp32 coupling out
        else                 pwrite_kernel<0><<<NDIM, 256>>>(P, Ph, Pl);  // bf16 split + mu
    }
}

// round 16
// speedup vs baseline: 1.3118x; 1.0041x over previous
#include <cuda_runtime.h>
#include <cuda_bf16.h>
#include <cstdint>
#include <cstddef>

#define NDIM 4096
#define DDIM 256
#define NMTOT ((size_t)NDIM * (size_t)NDIM)
#define EPS_R 0.05f
#define N_SINK 30
#define N_FGW 5

// ---------------- device scratch ----------------
__device__ float g_Dgen [NDIM * NDIM];
__device__ float g_Dreal[NDIM * NDIM];
__device__ float g_CW   [NDIM * NDIM];
__device__ float g_CGW  [NDIM * NDIM];
__device__ float g_Kmat [NDIM * NDIM];
__device__ __nv_bfloat16 g_Kb [NDIM * NDIM];   // bf16 K (Sinkhorn fast path)
__device__ __nv_bfloat16 g_Ktb[NDIM * NDIM];   // bf16 K^T
__device__ __nv_bfloat16 g_Dg_h[NDIM * NDIM], g_Dg_l[NDIM * NDIM];
__device__ __nv_bfloat16 g_Dr_h[NDIM * NDIM], g_Dr_l[NDIM * NDIM];
__device__ __nv_bfloat16 g_P_h [NDIM * NDIM], g_P_l [NDIM * NDIM];   // P split, row-major
__device__ __nv_bfloat16 g_W_h [NDIM * NDIM], g_W_l [NDIM * NDIM];   // W = Dreal*P^T
__device__ __nv_bfloat16 g_Fg_h[NDIM * DDIM], g_Fg_l[NDIM * DDIM];
__device__ __nv_bfloat16 g_Fr_h[NDIM * DDIM], g_Fr_l[NDIM * DDIM];
__device__ float g_x2g[NDIM], g_x2r[NDIM];
__device__ float g_sg2[NDIM], g_sr2[NDIM];
__device__ float g_rg [NDIM], g_rr [NDIM];
__device__ float g_mu [NDIM];
__device__ float g_u  [NDIM], g_v  [NDIM];
__device__ float g_part[8192];
__device__ float g_scal[8];   // 0:cwmax 1:gmax 2:cmax

// ---------------- helpers ----------------
__device__ __forceinline__ uint32_t pack2(float f0, float f1) {
    __nv_bfloat162 p; p.x = __float2bfloat16(f0); p.y = __float2bfloat16(f1);
    return *reinterpret_cast<uint32_t*>(&p);
}
__device__ __forceinline__ float2 bf2f(uint32_t p) {
    __nv_bfloat162 b = *reinterpret_cast<__nv_bfloat162*>(&p);
    return __bfloat1622float2(b);
}
__device__ __forceinline__ void ldm_x4(uint32_t* r, uint32_t a) {
    asm volatile("ldmatrix.sync.aligned.m8n8.x4.shared.b16 {%0,%1,%2,%3}, [%4];"
        : "=r"(r[0]), "=r"(r[1]), "=r"(r[2]), "=r"(r[3]) : "r"(a));
}
__device__ __forceinline__ void mma16816(float* c, const uint32_t* a, const uint32_t* b) {
    asm volatile("mma.sync.aligned.m16n8k16.row.col.f32.bf16.bf16.f32 "
        "{%0,%1,%2,%3}, {%4,%5,%6,%7}, {%8,%9}, {%0,%1,%2,%3};"
        : "+f"(c[0]), "+f"(c[1]), "+f"(c[2]), "+f"(c[3])
        : "r"(a[0]), "r"(a[1]), "r"(a[2]), "r"(a[3]), "r"(b[0]), "r"(b[1]));
}
__device__ __forceinline__ uint32_t smem_u32(const void* p) {
    uint32_t a;
    asm("{ .reg .u64 t; cvta.to.shared.u64 t, %1; cvt.u32.u64 %0, t; }" : "=r"(a) : "l"(p));
    return a;
}
__device__ __forceinline__ void split2(float x, __nv_bfloat16& h, __nv_bfloat16& l) {
    h = __float2bfloat16(x);
    l = __float2bfloat16(x - __bfloat162float(h));
}
#define CP16(dst, src) asm volatile("cp.async.cg.shared.global [%0], [%1], 16;" :: "r"(dst), "l"(src) : "memory")
#define CPC() asm volatile("cp.async.commit_group;" ::: "memory")
#define CPW(n) asm volatile("cp.async.wait_group %0;" :: "n"(n) : "memory")

// ---------------- reductions ----------------
template<int BS>
__device__ __forceinline__ float bsum(float v) {
    static __shared__ float sh[BS];
    int t = threadIdx.x;
    sh[t] = v; __syncthreads();
#pragma unroll
    for (int s = BS / 2; s >= 64; s >>= 1) { if (t < s) sh[t] += sh[t + s]; __syncthreads(); }
    float x = 0.f;
    if (t < 32) {
        x = sh[t] + sh[t + 32];
#pragma unroll
        for (int o = 16; o; o >>= 1) x += __shfl_down_sync(0xffffffffu, x, o);
    }
    return x;
}
template<int BS>
__device__ __forceinline__ float bmax(float v) {
    static __shared__ float sh[BS];
    int t = threadIdx.x;
    sh[t] = v; __syncthreads();
#pragma unroll
    for (int s = BS / 2; s >= 64; s >>= 1) { if (t < s) sh[t] = fmaxf(sh[t], sh[t + s]); __syncthreads(); }
    float x = -3.402823466e38f;
    if (t < 32) {
        x = fmaxf(sh[t], sh[t + 32]);
#pragma unroll
        for (int o = 16; o; o >>= 1) x = fmaxf(x, __shfl_down_sync(0xffffffffu, x, o));
    }
    return x;
}

// ---------------- 3-term split bf16 GEMM, two-level accumulation ----------
// C[m,n] = sum_k A[m,k]*B[n,k] (both operands K-major row-major).
// MODE 0: emit C re-split bf16 (W). 1: CGW epilogue + gmax (nu==1/NDIM).
// MODE 4: MODE 1 + also write Cfin = 0.5*CW + 0.5*CGW (fused cfinal).
// MODE 2: cdist sqrt epilogue (fp32). 3: CW relu epilogue + max.
#define STG_T 10240               // one tile: 128 rows * 80B (64B data + 16B pad)
#define STG_S (4 * STG_T)         // Ah,Al,Bh,Bl = 40960
#define SMEM_MM (3 * STG_S)       // 3 stages = 122880
#define BKT 32

template<int MODE, int NT, int LDK>
__global__ void __launch_bounds__(256, 1)
mma_gemm_kernel(const __nv_bfloat16* __restrict__ Ah_, const __nv_bfloat16* __restrict__ Al_,
                const __nv_bfloat16* __restrict__ Bh_, const __nv_bfloat16* __restrict__ Bl_,
                __nv_bfloat16* __restrict__ Oh, __nv_bfloat16* __restrict__ Ol,
                float* __restrict__ Cout, float* __restrict__ partials,
                const float* __restrict__ vx, const float* __restrict__ vy,
                float* __restrict__ Cfin)
{
    extern __shared__ char smem[];
    const uint32_t sb = smem_u32(smem);
    const int tid = threadIdx.x, warp = tid >> 5, lane = tid & 31;
    const int bm = blockIdx.y << 7, bn = blockIdx.x << 7;
    const int wm = (warp >> 2) << 6, wn = (warp & 3) << 5;  // warp tile 64x32

    const char* srcs[4] = {
        (const char*)(Ah_ + (size_t)bm * LDK), (const char*)(Al_ + (size_t)bm * LDK),
        (const char*)(Bh_ + (size_t)bn * LDK), (const char*)(Bl_ + (size_t)bn * LDK) };

    auto load_stage = [&](int slot, int kt) {
        const uint32_t sbase = sb + slot * STG_S;
        const size_t ko = (size_t)kt * (BKT * 2);
#pragma unroll
        for (int i = 0; i < 8; i++) {
            const int tile = i >> 1;
            const int wc = ((i & 1) << 8) + tid;        // 0..511 within tile
            const int row = wc >> 2, cc = wc & 3;
            uint32_t dst = sbase + tile * STG_T + row * 80 + (cc << 4);
            const char* src = srcs[tile] + (size_t)row * (LDK * 2) + ko + (cc << 4);
            CP16(dst, src);
        }
    };

    float acc[4][4][4], accS[4][4][4];
#pragma unroll
    for (int a = 0; a < 4; a++)
#pragma unroll
        for (int b = 0; b < 4; b++)
#pragma unroll
            for (int c = 0; c < 4; c++) { acc[a][b][c] = 0.f; accS[a][b][c] = 0.f; }

    load_stage(0, 0); CPC();
    load_stage(1, 1); CPC();

    const int grp = lane >> 3, l8 = lane & 7;

    for (int kt = 0; kt < NT; kt++) {
        CPW(1);
        __syncthreads();
        if (kt + 2 < NT) load_stage((kt + 2) % 3, kt + 2);
        CPC();
        const uint32_t stb = sb + (kt % 3) * STG_S;
#pragma unroll
        for (int ks = 0; ks < 2; ks++) {
            uint32_t ah[4][4], al[4][4], bh[4][2], bl[4][2], t[4];
            const uint32_t acol = (ks << 5) + ((grp >> 1) << 4);
#pragma unroll
            for (int mi = 0; mi < 4; mi++) {
                uint32_t ro = (uint32_t)(wm + (mi << 4) + ((grp & 1) << 3) + l8) * 80 + acol;
                ldm_x4(ah[mi], stb + 0 * STG_T + ro);
                ldm_x4(al[mi], stb + 1 * STG_T + ro);
            }
            const uint32_t bcol = (ks << 5) + ((grp & 1) << 4);
#pragma unroll
            for (int np = 0; np < 2; np++) {
                uint32_t ro = (uint32_t)(wn + (np << 4) + ((grp >> 1) << 3) + l8) * 80 + bcol;
                ldm_x4(t, stb + 2 * STG_T + ro);
                bh[2 * np][0] = t[0]; bh[2 * np][1] = t[1];
                bh[2 * np + 1][0] = t[2]; bh[2 * np + 1][1] = t[3];
                ldm_x4(t, stb + 3 * STG_T + ro);
                bl[2 * np][0] = t[0]; bl[2 * np][1] = t[1];
                bl[2 * np + 1][0] = t[2]; bl[2 * np + 1][1] = t[3];
            }
#pragma unroll
            for (int mi = 0; mi < 4; mi++)
#pragma unroll
                for (int ni = 0; ni < 4; ni++) {
                    mma16816(acc[mi][ni], ah[mi], bh[ni]);
                    mma16816(acc[mi][ni], ah[mi], bl[ni]);
                    mma16816(acc[mi][ni], al[mi], bh[ni]);
                }
        }
        if ((kt & 15) == 15 || kt == NT - 1) {   // pairwise flush (noise control)
#pragma unroll
            for (int a = 0; a < 4; a++)
#pragma unroll
                for (int b = 0; b < 4; b++)
#pragma unroll
                    for (int c = 0; c < 4; c++) { accS[a][b][c] += acc[a][b][c]; acc[a][b][c] = 0.f; }
        }
    }

    const float invn = 1.0f / NDIM;
    float lmax = 0.f;
#pragma unroll
    for (int mi = 0; mi < 4; mi++) {
        const int r1 = bm + wm + (mi << 4) + (lane >> 2);
        const int r2 = r1 + 8;
        float pA0 = 0.f, pA1 = 0.f, pB0 = 0.f, pB1 = 0.f;
        if (MODE == 1 || MODE == 4) { pA0 = g_sg2[r1]; pA1 = g_mu[r1]; pB0 = g_sg2[r2]; pB1 = g_mu[r2]; }
        if (MODE == 2 || MODE == 3) { pA0 = vx[r1]; pB0 = vx[r2]; }
#pragma unroll
        for (int ni = 0; ni < 4; ni++) {
            const int n1 = bn + wn + (ni << 3) + ((lane & 3) << 1);
            const float c0 = accS[mi][ni][0], c1 = accS[mi][ni][1];
            const float c2 = accS[mi][ni][2], c3 = accS[mi][ni][3];
            if (MODE == 0) {
                __nv_bfloat16 h0, l0, h1, l1;
                split2(c0, h0, l0); split2(c1, h1, l1);
                __nv_bfloat162 ll01{l0, l1};
                *(uint32_t*)(Oh + (size_t)r1 * NDIM + n1) = pack2(c0, c1);
                *(uint32_t*)(Ol + (size_t)r1 * NDIM + n1) = *(uint32_t*)&ll01;
                __nv_bfloat16 h2, l2, h3, l3;
                split2(c2, h2, l2); split2(c3, h3, l3);
                __nv_bfloat162 ll23{l2, l3};
                *(uint32_t*)(Oh + (size_t)r2 * NDIM + n1) = pack2(c2, c3);
                *(uint32_t*)(Ol + (size_t)r2 * NDIM + n1) = *(uint32_t*)&ll23;
            } else if (MODE == 1 || MODE == 4) {
                const float s1 = g_sr2[n1], s2 = g_sr2[n1 + 1];
                float v0 = pA0 * invn + pA1 * s1 - 2.f * c0;
                float v1 = pA0 * invn + pA1 * s2 - 2.f * c1;
                float v2 = pB0 * invn + pB1 * s1 - 2.f * c2;
                float v3 = pB0 * invn + pB1 * s2 - 2.f * c3;
                lmax = fmaxf(fmaxf(lmax, fabsf(v0)), fmaxf(fabsf(v1), fmaxf(fabsf(v2), fabsf(v3))));
                *(float2*)(Cout + (size_t)r1 * NDIM + n1) = make_float2(v0, v1);
                *(float2*)(Cout + (size_t)r2 * NDIM + n1) = make_float2(v2, v3);
                if (MODE == 4) {   // fused C_final = 0.5*CW + 0.5*CGW
                    float2 w1 = *(const float2*)(g_CW + (size_t)r1 * NDIM + n1);
                    float2 w2 = *(const float2*)(g_CW + (size_t)r2 * NDIM + n1);
                    *(float2*)(Cfin + (size_t)r1 * NDIM + n1) =
                        make_float2(0.5f * w1.x + 0.5f * v0, 0.5f * w1.y + 0.5f * v1);
                    *(float2*)(Cfin + (size_t)r2 * NDIM + n1) =
                        make_float2(0.5f * w2.x + 0.5f * v2, 0.5f * w2.y + 0.5f * v3);
                }
            } else {
                const float q1 = vy[n1], q2 = vy[n1 + 1];
                float d0 = fmaxf(pA0 + q1 - 2.f * c0, 0.f);
                float d1 = fmaxf(pA0 + q2 - 2.f * c1, 0.f);
                float d2 = fmaxf(pB0 + q1 - 2.f * c2, 0.f);
                float d3 = fmaxf(pB0 + q2 - 2.f * c3, 0.f);
                float v0, v1, v2, v3;
                if (MODE == 2) {
                    v0 = (d0 > 0.f) ? sqrtf(d0) : 0.f; v1 = (d1 > 0.f) ? sqrtf(d1) : 0.f;
                    v2 = (d2 > 0.f) ? sqrtf(d2) : 0.f; v3 = (d3 > 0.f) ? sqrtf(d3) : 0.f;
                } else {
                    v0 = d0; v1 = d1; v2 = d2; v3 = d3;
                    lmax = fmaxf(fmaxf(lmax, d0), fmaxf(d1, fmaxf(d2, d3)));
                }
                *(float2*)(Cout + (size_t)r1 * NDIM + n1) = make_float2(v0, v1);
                *(float2*)(Cout + (size_t)r2 * NDIM + n1) = make_float2(v2, v3);
            }
        }
    }
    if (MODE == 1 || MODE == 3 || MODE == 4) {
        float mm = bmax<256>(lmax);
        if (tid == 0) partials[blockIdx.y * gridDim.x + blockIdx.x] = mm;
    }
}

// ---------------- small kernels ----------------
__global__ void sqnorm_kernel(const float* __restrict__ X, float* __restrict__ out) {
    int i = blockIdx.x;
    float4 a = ((const float4*)(X + (size_t)i * DDIM))[threadIdx.x];
    float s = a.x * a.x + a.y * a.y + a.z * a.z + a.w * a.w;
    s = bsum<64>(s);
    if (threadIdx.x == 0) out[i] = s;
}

__global__ void row_sum_kernel(const float* __restrict__ M, float* __restrict__ out) {
    int i = blockIdx.x;
    const float4* rp = (const float4*)(M + (size_t)i * NDIM);
    float s = 0.f;
    for (int j = threadIdx.x; j < NDIM / 4; j += 256) { float4 a = rp[j]; s += a.x + a.y + a.z + a.w; }
    s = bsum<256>(s);
    if (threadIdx.x == 0) out[i] = s;
}

__global__ void row_sumsq_kernel(const float* __restrict__ M, float* __restrict__ out) {
    int i = blockIdx.x;
    const float4* rp = (const float4*)(M + (size_t)i * NDIM);
    float s = 0.f;
    for (int j = threadIdx.x; j < NDIM / 4; j += 256) {
        float4 a = rp[j];
        s += a.x * a.x + a.y * a.y + a.z * a.z + a.w * a.w;
    }
    s = bsum<256>(s);
    if (threadIdx.x == 0) out[i] = s;
}

// fp32 -> bf16 hi/lo, float4-wide
__global__ void split2_kernel(const float* __restrict__ src, __nv_bfloat16* __restrict__ dh,
                              __nv_bfloat16* __restrict__ dl, size_t n4) {
    size_t stride = (size_t)gridDim.x * blockDim.x;
    const float4* sp = (const float4*)src;
    uint2* hp = (uint2*)dh; uint2* lp = (uint2*)dl;
    for (size_t i = (size_t)blockIdx.x * blockDim.x + threadIdx.x; i < n4; i += stride) {
        float4 f = sp[i];
        __nv_bfloat16 h0, l0, h1, l1, h2, l2, h3, l3;
        split2(f.x, h0, l0); split2(f.y, h1, l1);
        split2(f.z, h2, l2); split2(f.w, h3, l3);
        __nv_bfloat162 hA{h0, h1}, hB{h2, h3}, lA{l0, l1}, lB{l2, l3};
        hp[i] = make_uint2(*(uint32_t*)&hA, *(uint32_t*)&hB);
        lp[i] = make_uint2(*(uint32_t*)&lA, *(uint32_t*)&lB);
    }
}

// bf16 K -> bf16 K^T (exact value copy); grid (128,128) x (32,8)
__global__ void transpose_bf16_kernel() {
    __shared__ __nv_bfloat16 tile[32][33];
    const int x0 = blockIdx.x << 5, y0 = blockIdx.y << 5;
    const int tx = threadIdx.x, ty = threadIdx.y;
#pragma unroll
    for (int r = ty; r < 32; r += 8)
        tile[r][tx] = g_Kb[(size_t)(y0 + r) * NDIM + x0 + tx];
    __syncthreads();
#pragma unroll
    for (int r = ty; r < 32; r += 8)
        g_Ktb[(size_t)(x0 + r) * NDIM + y0 + tx] = tile[tx][r];
}

// Sinkhorn: u_i = a / sum_j Kb[i,j] v_j  (bf16 K row pass)
__global__ void sink_row_kernel() {
    int i = blockIdx.x;
    const uint4* kr = (const uint4*)(g_Kb + (size_t)i * NDIM);   // 512 uint4 = 4096 bf16
    const float4* vv = (const float4*)g_v;
    float s = 0.f;
    for (int j = threadIdx.x; j < 512; j += 256) {
        uint4 k = kr[j];
        float4 v0 = vv[2 * j], v1 = vv[2 * j + 1];
        float2 a = bf2f(k.x), b = bf2f(k.y), c = bf2f(k.z), d = bf2f(k.w);
        s += a.x * v0.x + a.y * v0.y + b.x * v0.z + b.y * v0.w
           + c.x * v1.x + c.y * v1.y + d.x * v1.z + d.y * v1.w;
    }
    s = bsum<256>(s);
    if (threadIdx.x == 0) g_u[i] = (1.0f / NDIM) / s;
}

// Sinkhorn: v_j = b / sum_i Kb[i,j] u_i   (row pass over K^T)
__global__ void sink_col_kernel() {
    int j = blockIdx.x;
    const uint4* kr = (const uint4*)(g_Ktb + (size_t)j * NDIM);
    const float4* uu = (const float4*)g_u;
    float s = 0.f;
    for (int i = threadIdx.x; i < 512; i += 256) {
        uint4 k = kr[i];
        float4 u0 = uu[2 * i], u1 = uu[2 * i + 1];
        float2 a = bf2f(k.x), b = bf2f(k.y), c = bf2f(k.z), d = bf2f(k.w);
        s += a.x * u0.x + a.y * u0.y + b.x * u0.z + b.y * u0.w
           + c.x * u1.x + c.y * u1.y + d.x * u1.z + d.y * u1.w;
    }
    s = bsum<256>(s);
    if (threadIdx.x == 0) g_v[j] = (1.0f / NDIM) / s;
}

__global__ void gmax0_kernel(float* __restrict__ partials) {
    const int i = blockIdx.x;
    const float invn = 1.0f / NDIM;
    const float ai = g_sg2[i] * invn;
    const float gi = 2.0f * g_rg[i] * invn * invn;
    const float4* sp = (const float4*)g_sr2;
    const float4* rp = (const float4*)g_rr;
    float m = 0.f;
    for (int j = threadIdx.x; j < NDIM / 4; j += 256) {
        float4 s = sp[j], rr = rp[j];
        m = fmaxf(m, fabsf(ai + s.x * invn - gi * rr.x));
        m = fmaxf(m, fabsf(ai + s.y * invn - gi * rr.y));
        m = fmaxf(m, fabsf(ai + s.z * invn - gi * rr.z));
        m = fmaxf(m, fabsf(ai + s.w * invn - gi * rr.w));
    }
    m = bmax<256>(m);
    if (threadIdx.x == 0) partials[i] = m;
}

template<int ITER0>
__global__ void fusedmax_kernel(float* __restrict__ partials) {
    const int i = blockIdx.x;
    const float invcw = (g_scal[0] > 0.f) ? 1.f / g_scal[0] : 1.f;
    const float invg  = (g_scal[1] > 0.f) ? 1.f / g_scal[1] : 1.f;
    const float invn = 1.0f / NDIM;
    const float ai = g_sg2[i] * invn;
    const float gi = 2.0f * g_rg[i] * invn * invn;
    const float4* cwp = (const float4*)(g_CW + (size_t)i * NDIM);
    const float4* cgp = (const float4*)(g_CGW + (size_t)i * NDIM);
    const float4* sp = (const float4*)g_sr2;
    const float4* rp = (const float4*)g_rr;
    float m = -3.402823466e38f;
    for (int j = threadIdx.x; j < NDIM / 4; j += 256) {
        float4 cw = cwp[j], cg;
        if (ITER0) {
            float4 s = sp[j], rr = rp[j];
            cg.x = ai + s.x * invn - gi * rr.x; cg.y = ai + s.y * invn - gi * rr.y;
            cg.z = ai + s.z * invn - gi * rr.z; cg.w = ai + s.w * invn - gi * rr.w;
        } else cg = cgp[j];
        m = fmaxf(m, 0.5f * cw.x * invcw + 0.5f * cg.x * invg);
        m = fmaxf(m, 0.5f * cw.y * invcw + 0.5f * cg.y * invg);
        m = fmaxf(m, 0.5f * cw.z * invcw + 0.5f * cg.z * invg);
        m = fmaxf(m, 0.5f * cw.w * invcw + 0.5f * cg.w * invg);
    }
    m = bmax<256>(m);
    if (threadIdx.x == 0) partials[i] = m;
}

// K = exp(-C_fused/cmax/eps); writes fp32 K + bf16 K; inits v = 1 (blocks 0-15)
template<int ITER0>
__global__ void kexp_kernel() {
    const int i = blockIdx.x;
    if (i < 16) g_v[(i << 8) + threadIdx.x] = 1.0f;       // v init for Sinkhorn
    const float invcw = (g_scal[0] > 0.f) ? 1.f / g_scal[0] : 1.f;
    const float invg  = (g_scal[1] > 0.f) ? 1.f / g_scal[1] : 1.f;
    const float cm = g_scal[2];
    const float sc = (cm > 0.f) ? (-1.f / ((cm + 1e-8f) * EPS_R)) : (-1.f / EPS_R);
    const float invn = 1.0f / NDIM;
    const float ai = g_sg2[i] * invn;
    const float gi = 2.0f * g_rg[i] * invn * invn;
    const float4* cwp = (const float4*)(g_CW + (size_t)i * NDIM);
    const float4* cgp = (const float4*)(g_CGW + (size_t)i * NDIM);
    const float4* sp = (const float4*)g_sr2;
    const float4* rp = (const float4*)g_rr;
    float4* kp = (float4*)(g_Kmat + (size_t)i * NDIM);
    uint2* kbp = (uint2*)(g_Kb + (size_t)i * NDIM);
    for (int j = threadIdx.x; j < NDIM / 4; j += 256) {
        float4 cw = cwp[j], cg;
        if (ITER0) {
            float4 s = sp[j], rr = rp[j];
            cg.x = ai + s.x * invn - gi * rr.x; cg.y = ai + s.y * invn - gi * rr.y;
            cg.z = ai + s.z * invn - gi * rr.z; cg.w = ai + s.w * invn - gi * rr.w;
        } else cg = cgp[j];
        float4 o;
        o.x = __expf((0.5f * cw.x * invcw + 0.5f * cg.x * invg) * sc);
        o.y = __expf((0.5f * cw.y * invcw + 0.5f * cg.y * invg) * sc);
        o.z = __expf((0.5f * cw.z * invcw + 0.5f * cg.z * invg) * sc);
        o.w = __expf((0.5f * cw.w * invcw + 0.5f * cg.w * invg) * sc);
        kp[j] = o;
        kbp[j] = make_uint2(pack2(o.x, o.y), pack2(o.z, o.w));
    }
}

// P = u_i K_ij v_j (S == 1 + O(1e-6) by construction); fp32 K.
// FINAL=0: emit bf16 split of P (GEMM operand) + mu. FINAL=1: emit fp32 P.
template<int FINAL>
__global__ void pwrite_kernel(float* __restrict__ P,
                              __nv_bfloat16* __restrict__ Ph, __nv_bfloat16* __restrict__ Pl) {
    int i = blockIdx.x;
    float ui = g_u[i];
    const float4* kr = (const float4*)(g_Kmat + (size_t)i * NDIM);
    const float4* vv = (const float4*)g_v;
    float4* pr = (float4*)(P + (size_t)i * NDIM);
    uint2* hp = (uint2*)(Ph + (size_t)i * NDIM);
    uint2* lp = (uint2*)(Pl + (size_t)i * NDIM);
    float s = 0.f;
    for (int j = threadIdx.x; j < NDIM / 4; j += 256) {
        float4 k = kr[j], w = vv[j];
        float4 o;
        o.x = ui * k.x * w.x; o.y = ui * k.y * w.y; o.z = ui * k.z * w.z; o.w = ui * k.w * w.w;
        if (FINAL) {
            pr[j] = o;
        } else {
            __nv_bfloat16 h0, l0, h1, l1, h2, l2, h3, l3;
            split2(o.x, h0, l0); split2(o.y, h1, l1);
            split2(o.z, h2, l2); split2(o.w, h3, l3);
            __nv_bfloat162 hA{h0, h1}, hB{h2, h3}, lA{l0, l1}, lB{l2, l3};
            hp[j] = make_uint2(*(uint32_t*)&hA, *(uint32_t*)&hB);
            lp[j] = make_uint2(*(uint32_t*)&lA, *(uint32_t*)&lB);
        }
        s += o.x + o.y + o.z + o.w;
    }
    s = bsum<256>(s);
    if (threadIdx.x == 0) g_mu[i] = s;
}

__global__ void reduce_max_kernel(const float* __restrict__ part, int n, int slot) {
    float m = -3.402823466e38f;
    for (int i = threadIdx.x; i < n; i += 1024) m = fmaxf(m, part[i]);
    m = bmax<1024>(m);
    if (threadIdx.x == 0) g_scal[slot] = m;
}

// ---------------- launch --------------------------------------------------
extern "C" void kernel_launch(void* const* d_in, const int* in_sizes, int n_in,
                              void* d_out, int out_size) {
    const float* fg = (const float*)d_in[0];
    const float* fr = (const float*)d_in[1];
    float* P  = (float*)d_out;
    float* Cf = (float*)d_out + NMTOT;

    float *Dgen, *Dreal, *CW, *CGW, *x2g, *x2r, *sg2, *sr2, *rg, *rr, *part;
    __nv_bfloat16 *Dgh, *Dgl, *Drh, *Drl, *Ph, *Pl, *Wh, *Wl, *Fgh, *Fgl, *Frh, *Frl;
    cudaGetSymbolAddress((void**)&Dgen, g_Dgen);   cudaGetSymbolAddress((void**)&Dreal, g_Dreal);
    cudaGetSymbolAddress((void**)&CW, g_CW);       cudaGetSymbolAddress((void**)&CGW, g_CGW);
    cudaGetSymbolAddress((void**)&x2g, g_x2g);     cudaGetSymbolAddress((void**)&x2r, g_x2r);
    cudaGetSymbolAddress((void**)&sg2, g_sg2);     cudaGetSymbolAddress((void**)&sr2, g_sr2);
    cudaGetSymbolAddress((void**)&rg, g_rg);       cudaGetSymbolAddress((void**)&rr, g_rr);
    cudaGetSymbolAddress((void**)&part, g_part);
    cudaGetSymbolAddress((void**)&Dgh, g_Dg_h);    cudaGetSymbolAddress((void**)&Dgl, g_Dg_l);
    cudaGetSymbolAddress((void**)&Drh, g_Dr_h);    cudaGetSymbolAddress((void**)&Drl, g_Dr_l);
    cudaGetSymbolAddress((void**)&Ph, g_P_h);      cudaGetSymbolAddress((void**)&Pl, g_P_l);
    cudaGetSymbolAddress((void**)&Wh, g_W_h);      cudaGetSymbolAddress((void**)&Wl, g_W_l);
    cudaGetSymbolAddress((void**)&Fgh, g_Fg_h);    cudaGetSymbolAddress((void**)&Fgl, g_Fg_l);
    cudaGetSymbolAddress((void**)&Frh, g_Fr_h);    cudaGetSymbolAddress((void**)&Frl, g_Fr_l);

    cudaFuncSetAttribute((const void*)mma_gemm_kernel<0, 128, NDIM>, cudaFuncAttributeMaxDynamicSharedMemorySize, SMEM_MM);
    cudaFuncSetAttribute((const void*)mma_gemm_kernel<1, 128, NDIM>, cudaFuncAttributeMaxDynamicSharedMemorySize, SMEM_MM);
    cudaFuncSetAttribute((const void*)mma_gemm_kernel<4, 128, NDIM>, cudaFuncAttributeMaxDynamicSharedMemorySize, SMEM_MM);
    cudaFuncSetAttribute((const void*)mma_gemm_kernel<2, 8, DDIM>,  cudaFuncAttributeMaxDynamicSharedMemorySize, SMEM_MM);
    cudaFuncSetAttribute((const void*)mma_gemm_kernel<3, 8, DDIM>,  cudaFuncAttributeMaxDynamicSharedMemorySize, SMEM_MM);

    const dim3 gg(32, 32);
    const dim3 gtr(128, 128);
    const dim3 btr(32, 8);

    // feature norms + splits, cdist via tensor cores
    sqnorm_kernel<<<NDIM, 64>>>(fg, x2g);
    sqnorm_kernel<<<NDIM, 64>>>(fr, x2r);
    split2_kernel<<<512, 256>>>(fg, Fgh, Fgl, (size_t)NDIM * DDIM / 4);
    split2_kernel<<<512, 256>>>(fr, Frh, Frl, (size_t)NDIM * DDIM / 4);
    mma_gemm_kernel<2, 8, DDIM><<<gg, 256, SMEM_MM>>>(Fgh, Fgl, Fgh, Fgl, nullptr, nullptr, Dgen, nullptr, x2g, x2g, nullptr);
    mma_gemm_kernel<2, 8, DDIM><<<gg, 256, SMEM_MM>>>(Frh, Frl, Frh, Frl, nullptr, nullptr, Dreal, nullptr, x2r, x2r, nullptr);
    mma_gemm_kernel<3, 8, DDIM><<<gg, 256, SMEM_MM>>>(Fgh, Fgl, Frh, Frl, nullptr, nullptr, CW, part, x2g, x2r, nullptr);
    reduce_max_kernel<<<1, 1024>>>(part, 1024, 0);           // cwmax

    row_sumsq_kernel<<<NDIM, 256>>>(Dgen, sg2);
    row_sumsq_kernel<<<NDIM, 256>>>(Dreal, sr2);
    row_sum_kernel<<<NDIM, 256>>>(Dgen, rg);
    row_sum_kernel<<<NDIM, 256>>>(Dreal, rr);                // symmetric -> colsum
    split2_kernel<<<4096, 256>>>(Dgen, Dgh, Dgl, NMTOT / 4);
    split2_kernel<<<4096, 256>>>(Dreal, Drh, Drl, NMTOT / 4);  // symmetric -> B^T == B

    for (int it = 0; it < N_FGW; it++) {
        if (it == 0) {
            // coupling = a b^T is rank-1: closed-form CGW0
            gmax0_kernel<<<NDIM, 256>>>(part);
            reduce_max_kernel<<<1, 1024>>>(part, 4096, 1);   // gmax
            fusedmax_kernel<1><<<NDIM, 256>>>(part);
            reduce_max_kernel<<<1, 1024>>>(part, 4096, 2);   // cmax
            kexp_kernel<1><<<NDIM, 256>>>();
        } else {
            // no transpose: W = Dreal*P^T (B = P row-major); CGW = Dgen*W^T
            mma_gemm_kernel<0, 128, NDIM><<<gg, 256, SMEM_MM>>>(Drh, Drl, Ph, Pl, Wh, Wl, nullptr, nullptr, nullptr, nullptr, nullptr);
            if (it == N_FGW - 1)
                mma_gemm_kernel<4, 128, NDIM><<<gg, 256, SMEM_MM>>>(Dgh, Dgl, Wh, Wl, nullptr, nullptr, CGW, part, nullptr, nullptr, Cf);
            else
                mma_gemm_kernel<1, 128, NDIM><<<gg, 256, SMEM_MM>>>(Dgh, Dgl, Wh, Wl, nullptr, nullptr, CGW, part, nullptr, nullptr, nullptr);
            reduce_max_kernel<<<1, 1024>>>(part, 1024, 1);   // gmax
            fusedmax_kernel<0><<<NDIM, 256>>>(part);
            reduce_max_kernel<<<1, 1024>>>(part, 4096, 2);   // cmax
            kexp_kernel<0><<<NDIM, 256>>>();
        }
        // Sinkhorn on bf16 K + bf16 K^T (fp32 K kept for P); v init done in kexp
        transpose_bf16_kernel<<<gtr, btr>>>();
        for (int s = 0; s < N_SINK; s++) {
            sink_row_kernel<<<NDIM, 256>>>();
            sink_col_kernel<<<NDIM, 256>>>();
        }
        if (it == N_FGW - 1) pwrite_kernel<1><<<NDIM, 256>>>(P, Ph, Pl);  // fp32 coupling out
        else                 pwrite_kernel<0><<<NDIM, 256>>>(P, Ph, Pl);  // bf16 split + mu
    }
}